// round 15
// baseline (speedup 1.0000x reference)
#include <cuda_runtime.h>
#include <cuda_bf16.h>
#include <math.h>
#include <stdint.h>

#define BATCH 4
#define C_    192
#define H_    64
#define W_    64
#define HW    4096
#define HEADS 6
#define HID   768
#define KBIG  1728   // C_*9
#define NSPLIT 16

typedef __nv_bfloat16 bf16;
typedef unsigned long long u64;

// ---------------- scratch (static device globals; no allocation) ----------------
__device__ float g_xn  [(size_t)BATCH*C_*HW];
__device__ bf16  g_xnh [(size_t)BATCH*C_*HW];
__device__ bf16  g_xnl [(size_t)BATCH*C_*HW];
__device__ float g_off [(size_t)BATCH*18*HW];
__device__ bf16  g_samph[(size_t)BATCH*KBIG*HW];
__device__ bf16  g_sampl[(size_t)BATCH*KBIG*HW];
__device__ float g_kv  [(size_t)BATCH*2*C_*HW];
__device__ float g_norm[(size_t)BATCH*2*C_];      // reciprocal L2 norms of kv rows
__device__ float g_q   [(size_t)BATCH*C_*HW];
__device__ float g_spart[(size_t)BATCH*HEADS*NSPLIT*32*32];
__device__ float g_attn[(size_t)BATCH*HEADS*32*32];
__device__ bf16  g_aoh [(size_t)BATCH*C_*HW];
__device__ bf16  g_aol [(size_t)BATCH*C_*HW];
__device__ float g_proj[(size_t)BATCH*C_*HW];
__device__ float g_xs2 [(size_t)BATCH*C_*HW];
__device__ bf16  g_h1h [(size_t)BATCH*C_*HW];
__device__ bf16  g_h1l [(size_t)BATCH*C_*HW];
__device__ bf16  g_g1h [(size_t)BATCH*HID*HW];
__device__ bf16  g_g1l [(size_t)BATCH*HID*HW];
__device__ bf16  g_wkvh[384*C_],  g_wkvl[384*C_];
__device__ bf16  g_wdh [C_*KBIG], g_wdl [C_*KBIG];
__device__ bf16  g_wpjh[C_*C_],   g_wpjl[C_*C_];
__device__ bf16  g_w1h [HID*C_],  g_w1l [HID*C_];
__device__ bf16  g_w2h [C_*HID],  g_w2l [C_*HID];

__device__ __forceinline__ void split_store(float v, bf16* ph, bf16* pl) {
    bf16 h = __float2bfloat16(v);
    *ph = h;
    *pl = __float2bfloat16(v - __bfloat162float(h));
}

#define FMA_F32X2(d, a, b, c) \
    asm("fma.rn.f32x2 %0, %1, %2, %3;" : "=l"(d) : "l"(a), "l"(b), "l"(c))
#define PACK_F32X2(out, lo, hi) \
    asm("mov.b64 %0, {%1, %2};" : "=l"(out) : "f"(lo), "f"(hi))
#define UNPACK_F32X2(lo, hi, in) \
    asm("mov.b64 {%0, %1}, %2;" : "=f"(lo), "=f"(hi) : "l"(in))

// ---------------- merged weight convert ----------------
#define S1 (384*C_)
#define S2 (C_*KBIG)
#define S3 (C_*C_)
#define S4 (HID*C_)
#define S5 (C_*HID)
__global__ void convw_all(const float* __restrict__ wqkv, const float* __restrict__ wd,
                          const float* __restrict__ wproj, const float* __restrict__ wfc1,
                          const float* __restrict__ wfc2,
                          bf16* __restrict__ kvh, bf16* __restrict__ kvl,
                          bf16* __restrict__ dh,  bf16* __restrict__ dl,
                          bf16* __restrict__ pjh, bf16* __restrict__ pjl,
                          bf16* __restrict__ w1h, bf16* __restrict__ w1l,
                          bf16* __restrict__ w2h, bf16* __restrict__ w2l) {
    int i = blockIdx.x * 256 + threadIdx.x;
    if (i < S1) {
        split_store(wqkv[(size_t)C_ * C_ + i], kvh + i, kvl + i);
    } else if (i < S1 + S2) {
        int j = i - S1;
        split_store(wd[j], dh + j, dl + j);
    } else if (i < S1 + S2 + S3) {
        int j = i - S1 - S2;
        split_store(wproj[j], pjh + j, pjl + j);
    } else if (i < S1 + S2 + S3 + S4) {
        int j = i - S1 - S2 - S3;
        int m = j / C_, k = j - m * C_;
        split_store(wfc1[(size_t)k * HID + m], w1h + j, w1l + j);
    } else if (i < S1 + S2 + S3 + S4 + S5) {
        int j = i - S1 - S2 - S3 - S4;
        int m = j / HID, k = j - m * HID;
        split_store(wfc2[(size_t)k * C_ + m], w2h + j, w2l + j);
    }
}

// ---------------- LayerNorm over C, (B,C,HW): f32 + bf16 hi/lo outputs ----------------
__global__ void ln1_kernel(const float* __restrict__ x, const float* __restrict__ g,
                           const float* __restrict__ be, float* __restrict__ out,
                           bf16* __restrict__ oh, bf16* __restrict__ ol) {
    int b = blockIdx.x, hw0 = blockIdx.y * 32;
    __shared__ float tile[C_ * 33];
    __shared__ float mu[32], rs[32];
    int tid = threadIdx.x;
    const float* xb = x + (size_t)b * C_ * HW;
    #pragma unroll
    for (int i = 0; i < 24; i++) {
        int e = i * 256 + tid; int c = e >> 5; int p = e & 31;
        tile[c * 33 + p] = xb[(size_t)c * HW + hw0 + p];
    }
    __syncthreads();
    int warp = tid >> 5, lane = tid & 31;
    #pragma unroll
    for (int s = 0; s < 4; s++) {
        int p = warp * 4 + s;
        float v[6];
        #pragma unroll
        for (int k = 0; k < 6; k++) v[k] = tile[(lane + 32 * k) * 33 + p];
        float sum = 0.f;
        #pragma unroll
        for (int k = 0; k < 6; k++) sum += v[k];
        #pragma unroll
        for (int o = 16; o; o >>= 1) sum += __shfl_xor_sync(0xffffffffu, sum, o);
        float m = sum * (1.f / C_);
        float sq = 0.f;
        #pragma unroll
        for (int k = 0; k < 6; k++) { float d = v[k] - m; sq += d * d; }
        #pragma unroll
        for (int o = 16; o; o >>= 1) sq += __shfl_xor_sync(0xffffffffu, sq, o);
        if (lane == 0) { mu[p] = m; rs[p] = rsqrtf(sq * (1.f / C_) + 1e-5f); }
    }
    __syncthreads();
    #pragma unroll
    for (int i = 0; i < 24; i++) {
        int e = i * 256 + tid; int c = e >> 5; int p = e & 31;
        float v = (tile[c * 33 + p] - mu[p]) * rs[p] * g[c] + be[c];
        size_t o = (size_t)b * C_ * HW + (size_t)c * HW + hw0 + p;
        out[o] = v;
        split_store(v, oh + o, ol + o);
    }
}

// ---------------- residual add + LN2 (channel-major outputs) ----------------
__global__ void addln_kernel(const float* __restrict__ x, const float* __restrict__ pj,
                             const float* __restrict__ g, const float* __restrict__ be,
                             float* __restrict__ xs2, bf16* __restrict__ h1h,
                             bf16* __restrict__ h1l) {
    int b = blockIdx.x, hw0 = blockIdx.y * 32;
    __shared__ float tile[C_ * 33];
    __shared__ float mu[32], rs[32];
    int tid = threadIdx.x;
    const float* xb = x + (size_t)b * C_ * HW;
    const float* pb = pj + (size_t)b * C_ * HW;
    #pragma unroll
    for (int i = 0; i < 24; i++) {
        int e = i * 256 + tid; int c = e >> 5; int p = e & 31;
        tile[c * 33 + p] = xb[(size_t)c * HW + hw0 + p] + pb[(size_t)c * HW + hw0 + p];
    }
    __syncthreads();
    int warp = tid >> 5, lane = tid & 31;
    #pragma unroll
    for (int s = 0; s < 4; s++) {
        int p = warp * 4 + s;
        float v[6];
        #pragma unroll
        for (int k = 0; k < 6; k++) v[k] = tile[(lane + 32 * k) * 33 + p];
        float sum = 0.f;
        #pragma unroll
        for (int k = 0; k < 6; k++) sum += v[k];
        #pragma unroll
        for (int o = 16; o; o >>= 1) sum += __shfl_xor_sync(0xffffffffu, sum, o);
        float m = sum * (1.f / C_);
        float sq = 0.f;
        #pragma unroll
        for (int k = 0; k < 6; k++) { float d = v[k] - m; sq += d * d; }
        #pragma unroll
        for (int o = 16; o; o >>= 1) sq += __shfl_xor_sync(0xffffffffu, sq, o);
        if (lane == 0) { mu[p] = m; rs[p] = rsqrtf(sq * (1.f / C_) + 1e-5f); }
    }
    __syncthreads();
    #pragma unroll
    for (int i = 0; i < 24; i++) {
        int e = i * 256 + tid; int c = e >> 5; int p = e & 31;
        float v = tile[c * 33 + p];
        size_t o = (size_t)b * C_ * HW + (size_t)c * HW + hw0 + p;
        xs2[o] = v;
        float hn = (v - mu[p]) * rs[p] * g[c] + be[c];
        split_store(hn, h1h + o, h1l + o);
    }
}

// ---------------- 3x3 offset conv (18 ch), pad 1: packed f32x2 over channel pairs ----------------
__global__ void offconv_kernel(const float* __restrict__ xn, const float* __restrict__ wp,
                               const float* __restrict__ bp, float* __restrict__ off) {
    __shared__ float2 ws[16 * 162];
    int b = blockIdx.y;
    int h = blockIdx.x * 2 + (threadIdx.x >> 6);
    int w = threadIdx.x & 63;
    int tid = threadIdx.x;
    u64 acc[18];
    #pragma unroll
    for (int j = 0; j < 18; j++) acc[j] = 0ull;
    const float* xb = xn + (size_t)b * C_ * HW;
    for (int c0 = 0; c0 < C_; c0 += 32) {
        __syncthreads();
        for (int e = tid; e < 16 * 162; e += 128) {
            int pr = e / 162, jt = e - pr * 162;
            int j = jt / 9, t = jt - j * 9;
            int ce = c0 + pr * 2;
            ws[e] = make_float2(wp[((size_t)j * C_ + ce) * 9 + t],
                                wp[((size_t)j * C_ + ce + 1) * 9 + t]);
        }
        __syncthreads();
        for (int pr = 0; pr < 16; pr++) {
            const float* xc0 = xb + (size_t)(c0 + pr * 2) * HW;
            const float* xc1 = xc0 + HW;
            u64 vv[9];
            #pragma unroll
            for (int di = 0; di < 3; di++)
                #pragma unroll
                for (int dj = 0; dj < 3; dj++) {
                    int hh = h + di - 1, ww = w + dj - 1;
                    float a = 0.f, c = 0.f;
                    if (hh >= 0 && hh < H_ && ww >= 0 && ww < W_) {
                        a = __ldg(xc0 + hh * W_ + ww);
                        c = __ldg(xc1 + hh * W_ + ww);
                    }
                    PACK_F32X2(vv[di * 3 + dj], a, c);
                }
            const float2* wr = ws + pr * 162;
            #pragma unroll
            for (int j = 0; j < 18; j++)
                #pragma unroll
                for (int t = 0; t < 9; t++) {
                    u64 wv = *(const u64*)&wr[j * 9 + t];
                    FMA_F32X2(acc[j], wv, vv[t], acc[j]);
                }
        }
    }
    #pragma unroll
    for (int j = 0; j < 18; j++) {
        float lo, hi;
        UNPACK_F32X2(lo, hi, acc[j]);
        off[((size_t)b * 18 + j) * HW + h * W_ + w] = lo + hi + bp[j];
    }
}

// ---------------- deformable bilinear sampling, 2 pixels/thread, grid.z channel split ----------------
__global__ void deform_kernel(const float* __restrict__ xn, const float* __restrict__ off,
                              bf16* __restrict__ sh, bf16* __restrict__ sl) {
    int h = blockIdx.x, b = blockIdx.y;
    int cg = blockIdx.z * 8 + (threadIdx.x >> 5);
    int w = (threadIdx.x & 31) * 2;
    int hw = h * W_ + w;
    const float* xb = xn + (size_t)b * C_ * HW;
    const float* ob = off + (size_t)b * 18 * HW;
    bf16* sbh = sh + (size_t)b * KBIG * HW;
    bf16* sbl = sl + (size_t)b * KBIG * HW;
    const float HB = (float)(H_ + 1), WB = (float)(W_ + 1);
    for (int n = 0; n < 9; n++) {
        float g0[4], g1[4];
        int o0[4], o1[4];
        bool v0[4], v1[4];
        #pragma unroll
        for (int p = 0; p < 2; p++) {
            float ox = ob[(size_t)n * HW + hw + p];
            float oy = ob[(size_t)(9 + n) * HW + hw + p];
            float px = (float)(h + n / 3) + ox;
            float py = (float)(w + p + n % 3) + oy;
            float fx = floorf(px), fy = floorf(py);
            float qlx = fminf(fmaxf(fx, 0.f), HB);
            float qrx = fminf(fmaxf(fx + 1.f, 0.f), HB);
            float qly = fminf(fmaxf(fy, 0.f), WB);
            float qry = fminf(fmaxf(fy + 1.f, 0.f), WB);
            float pxc = fminf(fmaxf(px, 0.f), HB);
            float pyc = fminf(fmaxf(py, 0.f), WB);
            float glt = (1.f + qlx - pxc) * (1.f + qly - pyc);
            float grb = (1.f - qrx + pxc) * (1.f - qry + pyc);
            float glb = (1.f + qlx - pxc) * (1.f - qry + pyc);
            float grt = (1.f - qrx + pxc) * (1.f + qly - pyc);
            int ilx = (int)qlx, irx = (int)qrx, ily = (int)qly, iry = (int)qry;
            bool vlx = (ilx >= 1 && ilx <= H_), vrx = (irx >= 1 && irx <= H_);
            bool vly = (ily >= 1 && ily <= W_), vry = (iry >= 1 && iry <= W_);
            float* g = p ? g1 : g0; int* oo = p ? o1 : o0; bool* vb = p ? v1 : v0;
            g[0] = glt; oo[0] = (ilx - 1) * W_ + (ily - 1); vb[0] = vlx && vly;
            g[1] = grb; oo[1] = (irx - 1) * W_ + (iry - 1); vb[1] = vrx && vry;
            g[2] = glb; oo[2] = (ilx - 1) * W_ + (iry - 1); vb[2] = vlx && vry;
            g[3] = grt; oo[3] = (irx - 1) * W_ + (ily - 1); vb[3] = vrx && vly;
        }
        int c0 = cg * 6;
        #pragma unroll
        for (int c = c0; c < c0 + 6; c++) {
            const float* xc = xb + (size_t)c * HW;
            float a = 0.f, bb = 0.f;
            #pragma unroll
            for (int t = 0; t < 4; t++) {
                if (v0[t]) a  += g0[t] * __ldg(xc + o0[t]);
                if (v1[t]) bb += g1[t] * __ldg(xc + o1[t]);
            }
            size_t o = ((size_t)c * 9 + n) * HW + hw;
            bf16 ah = __float2bfloat16(a), bh = __float2bfloat16(bb);
            __nv_bfloat162 hv; hv.x = ah; hv.y = bh;
            __nv_bfloat162 lv;
            lv.x = __float2bfloat16(a - __bfloat162float(ah));
            lv.y = __float2bfloat16(bb - __bfloat162float(bh));
            *reinterpret_cast<__nv_bfloat162*>(sbh + o) = hv;
            *reinterpret_cast<__nv_bfloat162*>(sbl + o) = lv;
        }
    }
}

// ---------------- row L2 norms over HW -> reciprocal norms (no kv rewrite) ----------------
__global__ void norms_kernel(const float* __restrict__ kv, float* __restrict__ nrm) {
    int row = blockIdx.x;
    const float* p = kv + (size_t)row * HW;
    int tid = threadIdx.x;
    float s = 0.f;
    for (int i = tid; i < HW; i += 256) { float v = p[i]; s += v * v; }
    __shared__ float red[8];
    #pragma unroll
    for (int o = 16; o; o >>= 1) s += __shfl_xor_sync(0xffffffffu, s, o);
    if ((tid & 31) == 0) red[tid >> 5] = s;
    __syncthreads();
    if (tid == 0) {
        float t = 0.f;
        #pragma unroll
        for (int i = 0; i < 8; i++) t += red[i];
        nrm[row] = 1.f / fmaxf(sqrtf(t), 1e-12f);
    }
}

// ---------------- attention scores: split-K partials (raw kv) ----------------
__global__ void scores_part(const float* __restrict__ q, const float* __restrict__ kv,
                            float* __restrict__ spart) {
    int bh = blockIdx.x, s = blockIdx.y;
    int b = bh / HEADS, hh = bh % HEADS;
    int tid = threadIdx.x;
    int tx = tid & 15, ty = tid >> 4;
    __shared__ float qs[32 * 65], ks[32 * 65];
    const float* qrow = q + ((size_t)b * C_ + hh * 32) * HW;
    const float* krow = kv + ((size_t)b * 2 * C_ + hh * 32) * HW;
    float a00 = 0.f, a01 = 0.f, a10 = 0.f, a11 = 0.f;
    const int CH = HW / NSPLIT;
    for (int ch = s * CH; ch < s * CH + CH; ch += 64) {
        #pragma unroll
        for (int i = 0; i < 8; i++) {
            int e = i * 256 + tid; int r = e >> 6, col = e & 63;
            qs[r * 65 + col] = qrow[(size_t)r * HW + ch + col];
            ks[r * 65 + col] = krow[(size_t)r * HW + ch + col];
        }
        __syncthreads();
        #pragma unroll
        for (int t = 0; t < 64; t++) {
            float q0 = qs[(2 * ty) * 65 + t], q1 = qs[(2 * ty + 1) * 65 + t];
            float k0 = ks[(2 * tx) * 65 + t], k1 = ks[(2 * tx + 1) * 65 + t];
            a00 += q0 * k0; a01 += q0 * k1; a10 += q1 * k0; a11 += q1 * k1;
        }
        __syncthreads();
    }
    float* sp = spart + ((size_t)bh * NSPLIT + s) * 1024;
    sp[(2 * ty) * 32 + 2 * tx] = a00;
    sp[(2 * ty) * 32 + 2 * tx + 1] = a01;
    sp[(2 * ty + 1) * 32 + 2 * tx] = a10;
    sp[(2 * ty + 1) * 32 + 2 * tx + 1] = a11;
}

// ---------------- scores finalize: reduce + knorm + temp + softmax ----------------
__global__ void scores_fin(const float* __restrict__ spart, const float* __restrict__ temp,
                           const float* __restrict__ nrm, float* __restrict__ attn) {
    int bh = blockIdx.x, hh = bh % HEADS;
    int b = bh / HEADS;
    int d = threadIdx.x, c = threadIdx.y;
    float v = 0.f;
    #pragma unroll
    for (int s = 0; s < NSPLIT; s++)
        v += spart[(((size_t)bh * NSPLIT + s) * 32 + c) * 32 + d];
    v *= nrm[b * 2 * C_ + hh * 32 + d] * temp[hh];
    float m = v;
    #pragma unroll
    for (int o = 16; o; o >>= 1) m = fmaxf(m, __shfl_xor_sync(0xffffffffu, m, o));
    float e = expf(v - m);
    float su = e;
    #pragma unroll
    for (int o = 16; o; o >>= 1) su += __shfl_xor_sync(0xffffffffu, su, o);
    attn[((size_t)bh * 32 + c) * 32 + d] = e / su;
}

// ---------------- attention apply (vnorm folded into attn) -> bf16 hi/lo ----------------
__global__ void apply_kernel(const float* __restrict__ attn, const float* __restrict__ kv,
                             const float* __restrict__ nrm,
                             bf16* __restrict__ aoh, bf16* __restrict__ aol) {
    int bh = blockIdx.x; int b = bh / HEADS, hh = bh % HEADS;
    int tid = threadIdx.x;
    int n = blockIdx.y * 128 + tid;
    __shared__ float a[32][32];
    #pragma unroll
    for (int i = 0; i < 8; i++) {
        int e = i * 128 + tid;
        int dd = e & 31;
        a[e >> 5][dd] = attn[(size_t)bh * 1024 + e] * nrm[b * 2 * C_ + C_ + hh * 32 + dd];
    }
    __syncthreads();
    const float* vrow = kv + ((size_t)b * 2 * C_ + C_ + hh * 32) * HW;
    float acc[32];
    #pragma unroll
    for (int c = 0; c < 32; c++) acc[c] = 0.f;
    for (int dd = 0; dd < 32; dd++) {
        float v = vrow[(size_t)dd * HW + n];
        #pragma unroll
        for (int c = 0; c < 32; c++) acc[c] += a[c][dd] * v;
    }
    size_t ob = ((size_t)b * C_ + hh * 32) * HW + n;
    #pragma unroll
    for (int c = 0; c < 32; c++)
        split_store(acc[c], aoh + ob + (size_t)c * HW, aol + ob + (size_t)c * HW);
}

// ================= bf16 split tensor-core GEMM, NS-stage cp.async pipeline =================
// MI=3: BM=96, 3 stages (32KB/stage, 96KB/CTA, 2 CTAs/SM). MI=4: BM=128, 2 stages (75.8KB).
#define APITCH 40
#define BPITCH 136
#define BSTG (32 * BPITCH)
#define ASTG_OF(MI) ((MI) * 32 * APITCH)
#define NS_OF(MI) ((MI) == 3 ? 3 : 2)
#define SMEM_OF(MI) (NS_OF(MI) * (2 * ASTG_OF(MI) + 2 * BSTG) * 2)

__device__ __forceinline__ uint32_t cvta_s(const void* p) {
    return (uint32_t)__cvta_generic_to_shared(p);
}
__device__ __forceinline__ void cp_async16(uint32_t d, const void* s, int sz) {
    asm volatile("cp.async.cg.shared.global [%0], [%1], 16, %2;" :: "r"(d), "l"(s), "r"(sz));
}
__device__ __forceinline__ void cp_commit() { asm volatile("cp.async.commit_group;"); }
template<int N>
__device__ __forceinline__ void cp_waitn() { asm volatile("cp.async.wait_group %0;" :: "n"(N)); }

__device__ __forceinline__ void ldsm_x4(uint32_t* r, uint32_t a) {
    asm volatile("ldmatrix.sync.aligned.m8n8.x4.shared.b16 {%0,%1,%2,%3}, [%4];"
                 : "=r"(r[0]), "=r"(r[1]), "=r"(r[2]), "=r"(r[3]) : "r"(a));
}
__device__ __forceinline__ void ldsm_x4t(uint32_t* r, uint32_t a) {
    asm volatile("ldmatrix.sync.aligned.m8n8.x4.trans.shared.b16 {%0,%1,%2,%3}, [%4];"
                 : "=r"(r[0]), "=r"(r[1]), "=r"(r[2]), "=r"(r[3]) : "r"(a));
}
__device__ __forceinline__ void mma_bf16(float* c, const uint32_t* a, const uint32_t* b) {
    asm volatile("mma.sync.aligned.m16n8k16.row.col.f32.bf16.bf16.f32 "
                 "{%0,%1,%2,%3}, {%4,%5,%6,%7}, {%8,%9}, {%0,%1,%2,%3};"
                 : "+f"(c[0]), "+f"(c[1]), "+f"(c[2]), "+f"(c[3])
                 : "r"(a[0]), "r"(a[1]), "r"(a[2]), "r"(a[3]), "r"(b[0]), "r"(b[1]));
}

template<int EP, int MI>
__global__ void __launch_bounds__(256, 2)
mma_gemm(const bf16* __restrict__ Ah, const bf16* __restrict__ Al,
         const bf16* __restrict__ Bh, const bf16* __restrict__ Bl,
         int M, int N, int K,
         float* __restrict__ Cf, bf16* __restrict__ Oh, bf16* __restrict__ Ol,
         const float* __restrict__ bias, const float* __restrict__ res) {
    extern __shared__ char smem[];
    const int ASTG = ASTG_OF(MI);
    const int NS = NS_OF(MI);
    bf16* AsH = (bf16*)smem;
    bf16* AsL = AsH + NS * ASTG;
    bf16* BsH = AsL + NS * ASTG;
    bf16* BsL = BsH + NS * BSTG;
    const int BM = MI * 32;

    int z = blockIdx.z;
    size_t bOff = (size_t)z * K * N;
    size_t cOff = (size_t)z * M * N;
    int n0 = blockIdx.x * 128, m0 = blockIdx.y * BM;
    int tid = threadIdx.x, lane = tid & 31, warp = tid >> 5;
    int wm = (warp & 1) * (MI * 16), wn = (warp >> 1) * 32;
    float acc[MI][4][4];
    #pragma unroll
    for (int i = 0; i < MI; i++)
        #pragma unroll
        for (int j = 0; j < 4; j++)
            #pragma unroll
            for (int t = 0; t < 4; t++) acc[i][j][t] = 0.f;

    int nk = K >> 5;
    auto load_stage = [&](int st, int kt) {
        int k0 = kt << 5;
        bf16* aH = AsH + st * ASTG;
        bf16* aL = AsL + st * ASTG;
        bf16* bH = BsH + st * BSTG;
        bf16* bL = BsL + st * BSTG;
        #pragma unroll
        for (int i = 0; i < 2; i++) {
            int e = i * 256 + tid;
            if (e >= BM * 4) break;
            int r = e >> 2, qc = e & 3;
            int gr = m0 + r;
            int sz = (gr < M) ? 16 : 0;
            if (gr >= M) gr = M - 1;
            cp_async16(cvta_s(aH + r * APITCH + qc * 8), Ah + (size_t)gr * K + k0 + qc * 8, sz);
            cp_async16(cvta_s(aL + r * APITCH + qc * 8), Al + (size_t)gr * K + k0 + qc * 8, sz);
        }
        #pragma unroll
        for (int i = 0; i < 2; i++) {
            int e = i * 256 + tid;
            int r = e >> 4, qc = e & 15;
            const bf16* sH = Bh + bOff + (size_t)(k0 + r) * N + n0 + qc * 8;
            const bf16* sL = Bl + bOff + (size_t)(k0 + r) * N + n0 + qc * 8;
            cp_async16(cvta_s(bH + r * BPITCH + qc * 8), sH, 16);
            cp_async16(cvta_s(bL + r * BPITCH + qc * 8), sL, 16);
        }
    };

    // prefetch NS-1 stages
    #pragma unroll
    for (int s = 0; s < NS - 1; s++) {
        if (s < nk) { load_stage(s, s); cp_commit(); }
    }
    for (int kt = 0; kt < nk; kt++) {
        int st = kt % NS;
        bool more = (kt + NS - 1 < nk);
        if (more) { load_stage((kt + NS - 1) % NS, kt + NS - 1); cp_commit(); }
        if (more) cp_waitn<NS - 1>(); else cp_waitn<0>();
        __syncthreads();
        bf16* aH = AsH + st * ASTG;
        bf16* aL = AsL + st * ASTG;
        bf16* bH = BsH + st * BSTG;
        bf16* bL = BsL + st * BSTG;
        #pragma unroll
        for (int kk = 0; kk < 32; kk += 16) {
            uint32_t fbh[4][2], fbl[4][2];
            int brow = kk + (lane & 15);
            int nsel = (lane >> 4);
            #pragma unroll
            for (int ni = 0; ni < 4; ni += 2) {
                uint32_t tmp[4];
                ldsm_x4t(tmp, cvta_s(bH + brow * BPITCH + wn + (ni + nsel) * 8));
                fbh[ni][0] = tmp[0]; fbh[ni][1] = tmp[1];
                fbh[ni + 1][0] = tmp[2]; fbh[ni + 1][1] = tmp[3];
                ldsm_x4t(tmp, cvta_s(bL + brow * BPITCH + wn + (ni + nsel) * 8));
                fbl[ni][0] = tmp[0]; fbl[ni][1] = tmp[1];
                fbl[ni + 1][0] = tmp[2]; fbl[ni + 1][1] = tmp[3];
            }
            int arow = wm + (lane & 15);
            int acol = kk + ((lane >> 4) << 3);
            #pragma unroll
            for (int mi = 0; mi < MI; mi++) {
                uint32_t fah[4], fal[4];
                ldsm_x4(fah, cvta_s(aH + (arow + mi * 16) * APITCH + acol));
                ldsm_x4(fal, cvta_s(aL + (arow + mi * 16) * APITCH + acol));
                #pragma unroll
                for (int ni = 0; ni < 4; ni++) {
                    mma_bf16(acc[mi][ni], fah, fbh[ni]);
                    mma_bf16(acc[mi][ni], fah, fbl[ni]);
                    mma_bf16(acc[mi][ni], fal, fbh[ni]);
                }
            }
        }
        __syncthreads();
    }

    int gid = lane >> 2, tig = lane & 3;
    #pragma unroll
    for (int mi = 0; mi < MI; mi++) {
        #pragma unroll
        for (int ni = 0; ni < 4; ni++) {
            #pragma unroll
            for (int half = 0; half < 2; half++) {
                int row = m0 + wm + mi * 16 + gid + half * 8;
                if (row >= M) continue;
                int col = n0 + wn + ni * 8 + tig * 2;
                #pragma unroll
                for (int j = 0; j < 2; j++) {
                    float v = acc[mi][ni][half * 2 + j];
                    size_t o = cOff + (size_t)row * N + col + j;
                    if (EP == 0) {
                        Cf[o] = v;
                    } else if (EP == 1) {
                        v += bias[row];
                        v = 0.5f * v * (1.f + erff(v * 0.70710678118654752f));
                        split_store(v, Oh + o, Ol + o);
                    } else {
                        v += bias[row] + res[o];
                        Cf[o] = v;
                    }
                }
            }
        }
    }
}

// ---------------- launch (single stream) ----------------
extern "C" void kernel_launch(void* const* d_in, const int* in_sizes, int n_in,
                              void* d_out, int out_size) {
    const float* x     = (const float*)d_in[0];
    const float* ga1   = (const float*)d_in[1];
    const float* be1   = (const float*)d_in[2];
    const float* ga2   = (const float*)d_in[3];
    const float* be2   = (const float*)d_in[4];
    const float* temp  = (const float*)d_in[5];
    const float* wqkv  = (const float*)d_in[6];
    const float* wproj = (const float*)d_in[7];
    const float* wp    = (const float*)d_in[8];
    const float* bp    = (const float*)d_in[9];
    const float* wd    = (const float*)d_in[10];
    const float* wfc1  = (const float*)d_in[11];
    const float* bfc1  = (const float*)d_in[12];
    const float* wfc2  = (const float*)d_in[13];
    const float* bfc2  = (const float*)d_in[14];
    float* out = (float*)d_out;

    float *xn, *off, *kv, *nrm, *q, *spart, *attn, *proj, *xs2;
    bf16 *xnh, *xnl, *samph, *sampl, *aoh, *aol, *h1h, *h1l, *g1h, *g1l;
    bf16 *wkvh, *wkvl, *wdh, *wdl, *wpjh, *wpjl, *w1h, *w1l, *w2h, *w2l;
    cudaGetSymbolAddress((void**)&xn,    g_xn);
    cudaGetSymbolAddress((void**)&xnh,   g_xnh);
    cudaGetSymbolAddress((void**)&xnl,   g_xnl);
    cudaGetSymbolAddress((void**)&off,   g_off);
    cudaGetSymbolAddress((void**)&samph, g_samph);
    cudaGetSymbolAddress((void**)&sampl, g_sampl);
    cudaGetSymbolAddress((void**)&kv,    g_kv);
    cudaGetSymbolAddress((void**)&nrm,   g_norm);
    cudaGetSymbolAddress((void**)&q,     g_q);
    cudaGetSymbolAddress((void**)&spart, g_spart);
    cudaGetSymbolAddress((void**)&attn,  g_attn);
    cudaGetSymbolAddress((void**)&aoh,   g_aoh);
    cudaGetSymbolAddress((void**)&aol,   g_aol);
    cudaGetSymbolAddress((void**)&proj,  g_proj);
    cudaGetSymbolAddress((void**)&xs2,   g_xs2);
    cudaGetSymbolAddress((void**)&h1h,   g_h1h);
    cudaGetSymbolAddress((void**)&h1l,   g_h1l);
    cudaGetSymbolAddress((void**)&g1h,   g_g1h);
    cudaGetSymbolAddress((void**)&g1l,   g_g1l);
    cudaGetSymbolAddress((void**)&wkvh,  g_wkvh);
    cudaGetSymbolAddress((void**)&wkvl,  g_wkvl);
    cudaGetSymbolAddress((void**)&wdh,   g_wdh);
    cudaGetSymbolAddress((void**)&wdl,   g_wdl);
    cudaGetSymbolAddress((void**)&wpjh,  g_wpjh);
    cudaGetSymbolAddress((void**)&wpjl,  g_wpjl);
    cudaGetSymbolAddress((void**)&w1h,   g_w1h);
    cudaGetSymbolAddress((void**)&w1l,   g_w1l);
    cudaGetSymbolAddress((void**)&w2h,   g_w2h);
    cudaGetSymbolAddress((void**)&w2l,   g_w2l);

    cudaFuncSetAttribute(mma_gemm<0,4>, cudaFuncAttributeMaxDynamicSharedMemorySize, SMEM_OF(4));
    cudaFuncSetAttribute(mma_gemm<0,3>, cudaFuncAttributeMaxDynamicSharedMemorySize, SMEM_OF(3));
    cudaFuncSetAttribute(mma_gemm<1,4>, cudaFuncAttributeMaxDynamicSharedMemorySize, SMEM_OF(4));
    cudaFuncSetAttribute(mma_gemm<2,3>, cudaFuncAttributeMaxDynamicSharedMemorySize, SMEM_OF(3));

    int total = S1 + S2 + S3 + S4 + S5;
    convw_all<<<(total + 255) / 256, 256>>>(wqkv, wd, wproj, wfc1, wfc2,
                                            wkvh, wkvl, wdh, wdl, wpjh, wpjl,
                                            w1h, w1l, w2h, w2l);
    ln1_kernel<<<dim3(BATCH, HW / 32), 256>>>(x, ga1, be1, xn, xnh, xnl);
    offconv_kernel<<<dim3(32, BATCH), 128>>>(xn, wp, bp, off);
    deform_kernel<<<dim3(H_, BATCH, 4), 256>>>(xn, off, samph, sampl);
    // KV: M=384 -> MI=4 (2-stage)
    mma_gemm<0,4><<<dim3(32, 3, BATCH), 256, SMEM_OF(4)>>>(wkvh, wkvl, xnh, xnl, 384, HW, C_,
                                                           kv, nullptr, nullptr, nullptr, nullptr);
    // deform q: M=192 -> MI=3 (3-stage)
    mma_gemm<0,3><<<dim3(32, 2, BATCH), 256, SMEM_OF(3)>>>(wdh, wdl, samph, sampl, C_, HW, KBIG,
                                                           q, nullptr, nullptr, nullptr, nullptr);
    norms_kernel<<<BATCH * 2 * C_, 256>>>(kv, nrm);
    scores_part<<<dim3(BATCH * HEADS, NSPLIT), 256>>>(q, kv, spart);
    scores_fin<<<BATCH * HEADS, dim3(32, 32)>>>(spart, temp, nrm, attn);
    apply_kernel<<<dim3(BATCH * HEADS, HW / 128), 128>>>(attn, kv, nrm, aoh, aol);
    mma_gemm<0,3><<<dim3(32, 2, BATCH), 256, SMEM_OF(3)>>>(wpjh, wpjl, aoh, aol, C_, HW, C_,
                                                           proj, nullptr, nullptr, nullptr, nullptr);
    addln_kernel<<<dim3(BATCH, HW / 32), 256>>>(x, proj, ga2, be2, xs2, h1h, h1l);
    mma_gemm<1,4><<<dim3(32, 6, BATCH), 256, SMEM_OF(4)>>>(w1h, w1l, h1h, h1l, HID, HW, C_,
                                                           nullptr, g1h, g1l, bfc1, nullptr);
    mma_gemm<2,3><<<dim3(32, 2, BATCH), 256, SMEM_OF(3)>>>(w2h, w2l, g1h, g1l, C_, HW, HID,
                                                           out, nullptr, nullptr, bfc2, xs2);
}

// round 16
// speedup vs baseline: 1.5471x; 1.5471x over previous
#include <cuda_runtime.h>
#include <cuda_bf16.h>
#include <math.h>
#include <stdint.h>

#define BATCH 4
#define C_    192
#define H_    64
#define W_    64
#define HW    4096
#define HEADS 6
#define HID   768
#define KBIG  1728   // C_*9
#define NSPLIT 16

typedef __nv_bfloat16 bf16;
typedef unsigned long long u64;

// ---------------- scratch (static device globals; no allocation) ----------------
__device__ float g_xn  [(size_t)BATCH*C_*HW];
__device__ bf16  g_xnh [(size_t)BATCH*C_*HW];
__device__ bf16  g_xnl [(size_t)BATCH*C_*HW];
__device__ float g_off [(size_t)BATCH*18*HW];
__device__ bf16  g_samph[(size_t)BATCH*KBIG*HW];
__device__ bf16  g_sampl[(size_t)BATCH*KBIG*HW];
__device__ float g_kv  [(size_t)BATCH*2*C_*HW];
__device__ float g_norm[(size_t)BATCH*2*C_];      // reciprocal L2 norms of kv rows
__device__ float g_q   [(size_t)BATCH*C_*HW];
__device__ float g_spart[(size_t)BATCH*HEADS*NSPLIT*32*32];
__device__ float g_attn[(size_t)BATCH*HEADS*32*32];
__device__ bf16  g_aoh [(size_t)BATCH*C_*HW];
__device__ bf16  g_aol [(size_t)BATCH*C_*HW];
__device__ float g_proj[(size_t)BATCH*C_*HW];
__device__ float g_xs2 [(size_t)BATCH*C_*HW];
__device__ bf16  g_h1h [(size_t)BATCH*C_*HW];
__device__ bf16  g_h1l [(size_t)BATCH*C_*HW];
__device__ bf16  g_g1h [(size_t)BATCH*HID*HW];
__device__ bf16  g_g1l [(size_t)BATCH*HID*HW];
__device__ bf16  g_wkvh[384*C_],  g_wkvl[384*C_];
__device__ bf16  g_wdh [C_*KBIG], g_wdl [C_*KBIG];
__device__ bf16  g_wpjh[C_*C_],   g_wpjl[C_*C_];
__device__ bf16  g_w1h [HID*C_],  g_w1l [HID*C_];
__device__ bf16  g_w2h [C_*HID],  g_w2l [C_*HID];

__device__ __forceinline__ void split_store(float v, bf16* ph, bf16* pl) {
    bf16 h = __float2bfloat16(v);
    *ph = h;
    *pl = __float2bfloat16(v - __bfloat162float(h));
}

#define FMA_F32X2(d, a, b, c) \
    asm("fma.rn.f32x2 %0, %1, %2, %3;" : "=l"(d) : "l"(a), "l"(b), "l"(c))
#define PACK_F32X2(out, lo, hi) \
    asm("mov.b64 %0, {%1, %2};" : "=l"(out) : "f"(lo), "f"(hi))
#define UNPACK_F32X2(lo, hi, in) \
    asm("mov.b64 {%0, %1}, %2;" : "=f"(lo), "=f"(hi) : "l"(in))

// ---------------- merged weight convert ----------------
#define S1 (384*C_)
#define S2 (C_*KBIG)
#define S3 (C_*C_)
#define S4 (HID*C_)
#define S5 (C_*HID)
__global__ void convw_all(const float* __restrict__ wqkv, const float* __restrict__ wd,
                          const float* __restrict__ wproj, const float* __restrict__ wfc1,
                          const float* __restrict__ wfc2,
                          bf16* __restrict__ kvh, bf16* __restrict__ kvl,
                          bf16* __restrict__ dh,  bf16* __restrict__ dl,
                          bf16* __restrict__ pjh, bf16* __restrict__ pjl,
                          bf16* __restrict__ w1h, bf16* __restrict__ w1l,
                          bf16* __restrict__ w2h, bf16* __restrict__ w2l) {
    int i = blockIdx.x * 256 + threadIdx.x;
    if (i < S1) {
        split_store(wqkv[(size_t)C_ * C_ + i], kvh + i, kvl + i);
    } else if (i < S1 + S2) {
        int j = i - S1;
        split_store(wd[j], dh + j, dl + j);
    } else if (i < S1 + S2 + S3) {
        int j = i - S1 - S2;
        split_store(wproj[j], pjh + j, pjl + j);
    } else if (i < S1 + S2 + S3 + S4) {
        int j = i - S1 - S2 - S3;
        int m = j / C_, k = j - m * C_;
        split_store(wfc1[(size_t)k * HID + m], w1h + j, w1l + j);
    } else if (i < S1 + S2 + S3 + S4 + S5) {
        int j = i - S1 - S2 - S3 - S4;
        int m = j / HID, k = j - m * HID;
        split_store(wfc2[(size_t)k * C_ + m], w2h + j, w2l + j);
    }
}

// ---------------- LayerNorm over C, (B,C,HW): f32 + bf16 hi/lo outputs ----------------
__global__ void ln1_kernel(const float* __restrict__ x, const float* __restrict__ g,
                           const float* __restrict__ be, float* __restrict__ out,
                           bf16* __restrict__ oh, bf16* __restrict__ ol) {
    int b = blockIdx.x, hw0 = blockIdx.y * 32;
    __shared__ float tile[C_ * 33];
    __shared__ float mu[32], rs[32];
    int tid = threadIdx.x;
    const float* xb = x + (size_t)b * C_ * HW;
    #pragma unroll
    for (int i = 0; i < 24; i++) {
        int e = i * 256 + tid; int c = e >> 5; int p = e & 31;
        tile[c * 33 + p] = xb[(size_t)c * HW + hw0 + p];
    }
    __syncthreads();
    int warp = tid >> 5, lane = tid & 31;
    #pragma unroll
    for (int s = 0; s < 4; s++) {
        int p = warp * 4 + s;
        float v[6];
        #pragma unroll
        for (int k = 0; k < 6; k++) v[k] = tile[(lane + 32 * k) * 33 + p];
        float sum = 0.f;
        #pragma unroll
        for (int k = 0; k < 6; k++) sum += v[k];
        #pragma unroll
        for (int o = 16; o; o >>= 1) sum += __shfl_xor_sync(0xffffffffu, sum, o);
        float m = sum * (1.f / C_);
        float sq = 0.f;
        #pragma unroll
        for (int k = 0; k < 6; k++) { float d = v[k] - m; sq += d * d; }
        #pragma unroll
        for (int o = 16; o; o >>= 1) sq += __shfl_xor_sync(0xffffffffu, sq, o);
        if (lane == 0) { mu[p] = m; rs[p] = rsqrtf(sq * (1.f / C_) + 1e-5f); }
    }
    __syncthreads();
    #pragma unroll
    for (int i = 0; i < 24; i++) {
        int e = i * 256 + tid; int c = e >> 5; int p = e & 31;
        float v = (tile[c * 33 + p] - mu[p]) * rs[p] * g[c] + be[c];
        size_t o = (size_t)b * C_ * HW + (size_t)c * HW + hw0 + p;
        out[o] = v;
        split_store(v, oh + o, ol + o);
    }
}

// ---------------- residual add + LN2 (channel-major outputs) ----------------
__global__ void addln_kernel(const float* __restrict__ x, const float* __restrict__ pj,
                             const float* __restrict__ g, const float* __restrict__ be,
                             float* __restrict__ xs2, bf16* __restrict__ h1h,
                             bf16* __restrict__ h1l) {
    int b = blockIdx.x, hw0 = blockIdx.y * 32;
    __shared__ float tile[C_ * 33];
    __shared__ float mu[32], rs[32];
    int tid = threadIdx.x;
    const float* xb = x + (size_t)b * C_ * HW;
    const float* pb = pj + (size_t)b * C_ * HW;
    #pragma unroll
    for (int i = 0; i < 24; i++) {
        int e = i * 256 + tid; int c = e >> 5; int p = e & 31;
        tile[c * 33 + p] = xb[(size_t)c * HW + hw0 + p] + pb[(size_t)c * HW + hw0 + p];
    }
    __syncthreads();
    int warp = tid >> 5, lane = tid & 31;
    #pragma unroll
    for (int s = 0; s < 4; s++) {
        int p = warp * 4 + s;
        float v[6];
        #pragma unroll
        for (int k = 0; k < 6; k++) v[k] = tile[(lane + 32 * k) * 33 + p];
        float sum = 0.f;
        #pragma unroll
        for (int k = 0; k < 6; k++) sum += v[k];
        #pragma unroll
        for (int o = 16; o; o >>= 1) sum += __shfl_xor_sync(0xffffffffu, sum, o);
        float m = sum * (1.f / C_);
        float sq = 0.f;
        #pragma unroll
        for (int k = 0; k < 6; k++) { float d = v[k] - m; sq += d * d; }
        #pragma unroll
        for (int o = 16; o; o >>= 1) sq += __shfl_xor_sync(0xffffffffu, sq, o);
        if (lane == 0) { mu[p] = m; rs[p] = rsqrtf(sq * (1.f / C_) + 1e-5f); }
    }
    __syncthreads();
    #pragma unroll
    for (int i = 0; i < 24; i++) {
        int e = i * 256 + tid; int c = e >> 5; int p = e & 31;
        float v = tile[c * 33 + p];
        size_t o = (size_t)b * C_ * HW + (size_t)c * HW + hw0 + p;
        xs2[o] = v;
        float hn = (v - mu[p]) * rs[p] * g[c] + be[c];
        split_store(hn, h1h + o, h1l + o);
    }
}

// ---------------- 3x3 offset conv (18 ch), pad 1: packed f32x2 over channel pairs ----------------
__global__ void offconv_kernel(const float* __restrict__ xn, const float* __restrict__ wp,
                               const float* __restrict__ bp, float* __restrict__ off) {
    __shared__ float2 ws[16 * 162];
    int b = blockIdx.y;
    int h = blockIdx.x * 2 + (threadIdx.x >> 6);
    int w = threadIdx.x & 63;
    int tid = threadIdx.x;
    u64 acc[18];
    #pragma unroll
    for (int j = 0; j < 18; j++) acc[j] = 0ull;
    const float* xb = xn + (size_t)b * C_ * HW;
    for (int c0 = 0; c0 < C_; c0 += 32) {
        __syncthreads();
        for (int e = tid; e < 16 * 162; e += 128) {
            int pr = e / 162, jt = e - pr * 162;
            int j = jt / 9, t = jt - j * 9;
            int ce = c0 + pr * 2;
            ws[e] = make_float2(wp[((size_t)j * C_ + ce) * 9 + t],
                                wp[((size_t)j * C_ + ce + 1) * 9 + t]);
        }
        __syncthreads();
        for (int pr = 0; pr < 16; pr++) {
            const float* xc0 = xb + (size_t)(c0 + pr * 2) * HW;
            const float* xc1 = xc0 + HW;
            u64 vv[9];
            #pragma unroll
            for (int di = 0; di < 3; di++)
                #pragma unroll
                for (int dj = 0; dj < 3; dj++) {
                    int hh = h + di - 1, ww = w + dj - 1;
                    float a = 0.f, c = 0.f;
                    if (hh >= 0 && hh < H_ && ww >= 0 && ww < W_) {
                        a = __ldg(xc0 + hh * W_ + ww);
                        c = __ldg(xc1 + hh * W_ + ww);
                    }
                    PACK_F32X2(vv[di * 3 + dj], a, c);
                }
            const float2* wr = ws + pr * 162;
            #pragma unroll
            for (int j = 0; j < 18; j++)
                #pragma unroll
                for (int t = 0; t < 9; t++) {
                    u64 wv = *(const u64*)&wr[j * 9 + t];
                    FMA_F32X2(acc[j], wv, vv[t], acc[j]);
                }
        }
    }
    #pragma unroll
    for (int j = 0; j < 18; j++) {
        float lo, hi;
        UNPACK_F32X2(lo, hi, acc[j]);
        off[((size_t)b * 18 + j) * HW + h * W_ + w] = lo + hi + bp[j];
    }
}

// ---------------- deformable bilinear sampling, 2 pixels/thread, grid.z channel split ----------------
__global__ void deform_kernel(const float* __restrict__ xn, const float* __restrict__ off,
                              bf16* __restrict__ sh, bf16* __restrict__ sl) {
    int h = blockIdx.x, b = blockIdx.y;
    int cg = blockIdx.z * 8 + (threadIdx.x >> 5);   // 64 groups of 3 channels
    int w = (threadIdx.x & 31) * 2;
    int hw = h * W_ + w;
    const float* xb = xn + (size_t)b * C_ * HW;
    const float* ob = off + (size_t)b * 18 * HW;
    bf16* sbh = sh + (size_t)b * KBIG * HW;
    bf16* sbl = sl + (size_t)b * KBIG * HW;
    const float HB = (float)(H_ + 1), WB = (float)(W_ + 1);
    for (int n = 0; n < 9; n++) {
        float g0[4], g1[4];
        int o0[4], o1[4];
        bool v0[4], v1[4];
        #pragma unroll
        for (int p = 0; p < 2; p++) {
            float ox = ob[(size_t)n * HW + hw + p];
            float oy = ob[(size_t)(9 + n) * HW + hw + p];
            float px = (float)(h + n / 3) + ox;
            float py = (float)(w + p + n % 3) + oy;
            float fx = floorf(px), fy = floorf(py);
            float qlx = fminf(fmaxf(fx, 0.f), HB);
            float qrx = fminf(fmaxf(fx + 1.f, 0.f), HB);
            float qly = fminf(fmaxf(fy, 0.f), WB);
            float qry = fminf(fmaxf(fy + 1.f, 0.f), WB);
            float pxc = fminf(fmaxf(px, 0.f), HB);
            float pyc = fminf(fmaxf(py, 0.f), WB);
            float glt = (1.f + qlx - pxc) * (1.f + qly - pyc);
            float grb = (1.f - qrx + pxc) * (1.f - qry + pyc);
            float glb = (1.f + qlx - pxc) * (1.f - qry + pyc);
            float grt = (1.f - qrx + pxc) * (1.f + qly - pyc);
            int ilx = (int)qlx, irx = (int)qrx, ily = (int)qly, iry = (int)qry;
            bool vlx = (ilx >= 1 && ilx <= H_), vrx = (irx >= 1 && irx <= H_);
            bool vly = (ily >= 1 && ily <= W_), vry = (iry >= 1 && iry <= W_);
            float* g = p ? g1 : g0; int* oo = p ? o1 : o0; bool* vb = p ? v1 : v0;
            g[0] = glt; oo[0] = (ilx - 1) * W_ + (ily - 1); vb[0] = vlx && vly;
            g[1] = grb; oo[1] = (irx - 1) * W_ + (iry - 1); vb[1] = vrx && vry;
            g[2] = glb; oo[2] = (ilx - 1) * W_ + (iry - 1); vb[2] = vlx && vry;
            g[3] = grt; oo[3] = (irx - 1) * W_ + (ily - 1); vb[3] = vrx && vly;
        }
        int c0 = cg * 3;
        #pragma unroll
        for (int c = c0; c < c0 + 3; c++) {
            const float* xc = xb + (size_t)c * HW;
            float a = 0.f, bb = 0.f;
            #pragma unroll
            for (int t = 0; t < 4; t++) {
                if (v0[t]) a  += g0[t] * __ldg(xc + o0[t]);
                if (v1[t]) bb += g1[t] * __ldg(xc + o1[t]);
            }
            size_t o = ((size_t)c * 9 + n) * HW + hw;
            bf16 ah = __float2bfloat16(a), bh = __float2bfloat16(bb);
            __nv_bfloat162 hv; hv.x = ah; hv.y = bh;
            __nv_bfloat162 lv;
            lv.x = __float2bfloat16(a - __bfloat162float(ah));
            lv.y = __float2bfloat16(bb - __bfloat162float(bh));
            *reinterpret_cast<__nv_bfloat162*>(sbh + o) = hv;
            *reinterpret_cast<__nv_bfloat162*>(sbl + o) = lv;
        }
    }
}

// ---------------- row L2 norms over HW -> reciprocal norms (no kv rewrite) ----------------
__global__ void norms_kernel(const float* __restrict__ kv, float* __restrict__ nrm) {
    int row = blockIdx.x;
    const float* p = kv + (size_t)row * HW;
    int tid = threadIdx.x;
    float s = 0.f;
    for (int i = tid; i < HW; i += 256) { float v = p[i]; s += v * v; }
    __shared__ float red[8];
    #pragma unroll
    for (int o = 16; o; o >>= 1) s += __shfl_xor_sync(0xffffffffu, s, o);
    if ((tid & 31) == 0) red[tid >> 5] = s;
    __syncthreads();
    if (tid == 0) {
        float t = 0.f;
        #pragma unroll
        for (int i = 0; i < 8; i++) t += red[i];
        nrm[row] = 1.f / fmaxf(sqrtf(t), 1e-12f);
    }
}

// ---------------- attention scores: split-K partials (raw kv) ----------------
__global__ void scores_part(const float* __restrict__ q, const float* __restrict__ kv,
                            float* __restrict__ spart) {
    int bh = blockIdx.x, s = blockIdx.y;
    int b = bh / HEADS, hh = bh % HEADS;
    int tid = threadIdx.x;
    int tx = tid & 15, ty = tid >> 4;
    __shared__ float qs[32 * 65], ks[32 * 65];
    const float* qrow = q + ((size_t)b * C_ + hh * 32) * HW;
    const float* krow = kv + ((size_t)b * 2 * C_ + hh * 32) * HW;
    float a00 = 0.f, a01 = 0.f, a10 = 0.f, a11 = 0.f;
    const int CH = HW / NSPLIT;
    for (int ch = s * CH; ch < s * CH + CH; ch += 64) {
        #pragma unroll
        for (int i = 0; i < 8; i++) {
            int e = i * 256 + tid; int r = e >> 6, col = e & 63;
            qs[r * 65 + col] = qrow[(size_t)r * HW + ch + col];
            ks[r * 65 + col] = krow[(size_t)r * HW + ch + col];
        }
        __syncthreads();
        #pragma unroll
        for (int t = 0; t < 64; t++) {
            float q0 = qs[(2 * ty) * 65 + t], q1 = qs[(2 * ty + 1) * 65 + t];
            float k0 = ks[(2 * tx) * 65 + t], k1 = ks[(2 * tx + 1) * 65 + t];
            a00 += q0 * k0; a01 += q0 * k1; a10 += q1 * k0; a11 += q1 * k1;
        }
        __syncthreads();
    }
    float* sp = spart + ((size_t)bh * NSPLIT + s) * 1024;
    sp[(2 * ty) * 32 + 2 * tx] = a00;
    sp[(2 * ty) * 32 + 2 * tx + 1] = a01;
    sp[(2 * ty + 1) * 32 + 2 * tx] = a10;
    sp[(2 * ty + 1) * 32 + 2 * tx + 1] = a11;
}

// ---------------- scores finalize: reduce + knorm + temp + softmax ----------------
__global__ void scores_fin(const float* __restrict__ spart, const float* __restrict__ temp,
                           const float* __restrict__ nrm, float* __restrict__ attn) {
    int bh = blockIdx.x, hh = bh % HEADS;
    int b = bh / HEADS;
    int d = threadIdx.x, c = threadIdx.y;
    float v = 0.f;
    #pragma unroll
    for (int s = 0; s < NSPLIT; s++)
        v += spart[(((size_t)bh * NSPLIT + s) * 32 + c) * 32 + d];
    v *= nrm[b * 2 * C_ + hh * 32 + d] * temp[hh];
    float m = v;
    #pragma unroll
    for (int o = 16; o; o >>= 1) m = fmaxf(m, __shfl_xor_sync(0xffffffffu, m, o));
    float e = expf(v - m);
    float su = e;
    #pragma unroll
    for (int o = 16; o; o >>= 1) su += __shfl_xor_sync(0xffffffffu, su, o);
    attn[((size_t)bh * 32 + c) * 32 + d] = e / su;
}

// ---------------- attention apply (vnorm folded into attn) -> bf16 hi/lo ----------------
__global__ void apply_kernel(const float* __restrict__ attn, const float* __restrict__ kv,
                             const float* __restrict__ nrm,
                             bf16* __restrict__ aoh, bf16* __restrict__ aol) {
    int bh = blockIdx.x; int b = bh / HEADS, hh = bh % HEADS;
    int tid = threadIdx.x;
    int n = blockIdx.y * 128 + tid;
    __shared__ float a[32][32];
    #pragma unroll
    for (int i = 0; i < 8; i++) {
        int e = i * 128 + tid;
        int dd = e & 31;
        a[e >> 5][dd] = attn[(size_t)bh * 1024 + e] * nrm[b * 2 * C_ + C_ + hh * 32 + dd];
    }
    __syncthreads();
    const float* vrow = kv + ((size_t)b * 2 * C_ + C_ + hh * 32) * HW;
    float acc[32];
    #pragma unroll
    for (int c = 0; c < 32; c++) acc[c] = 0.f;
    for (int dd = 0; dd < 32; dd++) {
        float v = vrow[(size_t)dd * HW + n];
        #pragma unroll
        for (int c = 0; c < 32; c++) acc[c] += a[c][dd] * v;
    }
    size_t ob = ((size_t)b * C_ + hh * 32) * HW + n;
    #pragma unroll
    for (int c = 0; c < 32; c++)
        split_store(acc[c], aoh + ob + (size_t)c * HW, aol + ob + (size_t)c * HW);
}

// ================= bf16 split tensor-core GEMM with 2-stage cp.async pipeline =================
#define APITCH 40
#define BPITCH 136
#define ASTG (128 * APITCH)
#define BSTG (32 * BPITCH)
#define SMEM_GEMM ((2 * ASTG * 2 + 2 * BSTG * 2) * 2)  // bytes: 75776

__device__ __forceinline__ uint32_t cvta_s(const void* p) {
    return (uint32_t)__cvta_generic_to_shared(p);
}
__device__ __forceinline__ void cp_async16(uint32_t d, const void* s, int sz) {
    asm volatile("cp.async.cg.shared.global [%0], [%1], 16, %2;" :: "r"(d), "l"(s), "r"(sz));
}
__device__ __forceinline__ void cp_commit() { asm volatile("cp.async.commit_group;"); }
__device__ __forceinline__ void cp_wait1() { asm volatile("cp.async.wait_group 1;"); }
__device__ __forceinline__ void cp_wait0() { asm volatile("cp.async.wait_group 0;"); }

__device__ __forceinline__ void ldsm_x4(uint32_t* r, uint32_t a) {
    asm volatile("ldmatrix.sync.aligned.m8n8.x4.shared.b16 {%0,%1,%2,%3}, [%4];"
                 : "=r"(r[0]), "=r"(r[1]), "=r"(r[2]), "=r"(r[3]) : "r"(a));
}
__device__ __forceinline__ void ldsm_x4t(uint32_t* r, uint32_t a) {
    asm volatile("ldmatrix.sync.aligned.m8n8.x4.trans.shared.b16 {%0,%1,%2,%3}, [%4];"
                 : "=r"(r[0]), "=r"(r[1]), "=r"(r[2]), "=r"(r[3]) : "r"(a));
}
__device__ __forceinline__ void mma_bf16(float* c, const uint32_t* a, const uint32_t* b) {
    asm volatile("mma.sync.aligned.m16n8k16.row.col.f32.bf16.bf16.f32 "
                 "{%0,%1,%2,%3}, {%4,%5,%6,%7}, {%8,%9}, {%0,%1,%2,%3};"
                 : "+f"(c[0]), "+f"(c[1]), "+f"(c[2]), "+f"(c[3])
                 : "r"(a[0]), "r"(a[1]), "r"(a[2]), "r"(a[3]), "r"(b[0]), "r"(b[1]));
}

template<int EP, int MI>
__global__ void __launch_bounds__(256, 2)
mma_gemm(const bf16* __restrict__ Ah, const bf16* __restrict__ Al,
         const bf16* __restrict__ Bh, const bf16* __restrict__ Bl,
         int M, int N, int K,
         float* __restrict__ Cf, bf16* __restrict__ Oh, bf16* __restrict__ Ol,
         const float* __restrict__ bias, const float* __restrict__ res) {
    extern __shared__ char smem[];
    bf16* AsH = (bf16*)smem;
    bf16* AsL = AsH + 2 * ASTG;
    bf16* BsH = AsL + 2 * ASTG;
    bf16* BsL = BsH + 2 * BSTG;
    const int BM = MI * 32;

    int z = blockIdx.z;
    size_t bOff = (size_t)z * K * N;
    size_t cOff = (size_t)z * M * N;
    int n0 = blockIdx.x * 128, m0 = blockIdx.y * BM;
    int tid = threadIdx.x, lane = tid & 31, warp = tid >> 5;
    int wm = (warp & 1) * (MI * 16), wn = (warp >> 1) * 32;
    float acc[MI][4][4];
    #pragma unroll
    for (int i = 0; i < MI; i++)
        #pragma unroll
        for (int j = 0; j < 4; j++)
            #pragma unroll
            for (int t = 0; t < 4; t++) acc[i][j][t] = 0.f;

    int nk = K >> 5;
    auto load_stage = [&](int st, int kt) {
        int k0 = kt << 5;
        bf16* aH = AsH + st * ASTG;
        bf16* aL = AsL + st * ASTG;
        bf16* bH = BsH + st * BSTG;
        bf16* bL = BsL + st * BSTG;
        #pragma unroll
        for (int i = 0; i < 2; i++) {
            int e = i * 256 + tid;
            if (e >= BM * 4) break;
            int r = e >> 2, qc = e & 3;
            int gr = m0 + r;
            int sz = (gr < M) ? 16 : 0;
            if (gr >= M) gr = M - 1;
            cp_async16(cvta_s(aH + r * APITCH + qc * 8), Ah + (size_t)gr * K + k0 + qc * 8, sz);
            cp_async16(cvta_s(aL + r * APITCH + qc * 8), Al + (size_t)gr * K + k0 + qc * 8, sz);
        }
        #pragma unroll
        for (int i = 0; i < 2; i++) {
            int e = i * 256 + tid;
            int r = e >> 4, qc = e & 15;
            const bf16* sH = Bh + bOff + (size_t)(k0 + r) * N + n0 + qc * 8;
            const bf16* sL = Bl + bOff + (size_t)(k0 + r) * N + n0 + qc * 8;
            cp_async16(cvta_s(bH + r * BPITCH + qc * 8), sH, 16);
            cp_async16(cvta_s(bL + r * BPITCH + qc * 8), sL, 16);
        }
    };

    load_stage(0, 0);
    cp_commit();
    for (int kt = 0; kt < nk; kt++) {
        int st = kt & 1;
        bool more = (kt + 1 < nk);
        if (more) { load_stage(st ^ 1, kt + 1); cp_commit(); }
        if (more) cp_wait1(); else cp_wait0();
        __syncthreads();
        bf16* aH = AsH + st * ASTG;
        bf16* aL = AsL + st * ASTG;
        bf16* bH = BsH + st * BSTG;
        bf16* bL = BsL + st * BSTG;
        #pragma unroll
        for (int kk = 0; kk < 32; kk += 16) {
            uint32_t fbh[4][2], fbl[4][2];
            int brow = kk + (lane & 15);
            int nsel = (lane >> 4);
            #pragma unroll
            for (int ni = 0; ni < 4; ni += 2) {
                uint32_t tmp[4];
                ldsm_x4t(tmp, cvta_s(bH + brow * BPITCH + wn + (ni + nsel) * 8));
                fbh[ni][0] = tmp[0]; fbh[ni][1] = tmp[1];
                fbh[ni + 1][0] = tmp[2]; fbh[ni + 1][1] = tmp[3];
                ldsm_x4t(tmp, cvta_s(bL + brow * BPITCH + wn + (ni + nsel) * 8));
                fbl[ni][0] = tmp[0]; fbl[ni][1] = tmp[1];
                fbl[ni + 1][0] = tmp[2]; fbl[ni + 1][1] = tmp[3];
            }
            int arow = wm + (lane & 15);
            int acol = kk + ((lane >> 4) << 3);
            #pragma unroll
            for (int mi = 0; mi < MI; mi++) {
                uint32_t fah[4], fal[4];
                ldsm_x4(fah, cvta_s(aH + (arow + mi * 16) * APITCH + acol));
                ldsm_x4(fal, cvta_s(aL + (arow + mi * 16) * APITCH + acol));
                #pragma unroll
                for (int ni = 0; ni < 4; ni++) {
                    mma_bf16(acc[mi][ni], fah, fbh[ni]);
                    mma_bf16(acc[mi][ni], fah, fbl[ni]);
                    mma_bf16(acc[mi][ni], fal, fbh[ni]);
                }
            }
        }
        __syncthreads();
    }

    int gid = lane >> 2, tig = lane & 3;
    #pragma unroll
    for (int mi = 0; mi < MI; mi++) {
        #pragma unroll
        for (int ni = 0; ni < 4; ni++) {
            #pragma unroll
            for (int half = 0; half < 2; half++) {
                int row = m0 + wm + mi * 16 + gid + half * 8;
                if (row >= M) continue;
                int col = n0 + wn + ni * 8 + tig * 2;
                #pragma unroll
                for (int j = 0; j < 2; j++) {
                    float v = acc[mi][ni][half * 2 + j];
                    size_t o = cOff + (size_t)row * N + col + j;
                    if (EP == 0) {
                        Cf[o] = v;
                    } else if (EP == 1) {
                        v += bias[row];
                        v = 0.5f * v * (1.f + erff(v * 0.70710678118654752f));
                        split_store(v, Oh + o, Ol + o);
                    } else {
                        v += bias[row] + res[o];
                        Cf[o] = v;
                    }
                }
            }
        }
    }
}

// ---------------- launch (single stream) ----------------
extern "C" void kernel_launch(void* const* d_in, const int* in_sizes, int n_in,
                              void* d_out, int out_size) {
    const float* x     = (const float*)d_in[0];
    const float* ga1   = (const float*)d_in[1];
    const float* be1   = (const float*)d_in[2];
    const float* ga2   = (const float*)d_in[3];
    const float* be2   = (const float*)d_in[4];
    const float* temp  = (const float*)d_in[5];
    const float* wqkv  = (const float*)d_in[6];
    const float* wproj = (const float*)d_in[7];
    const float* wp    = (const float*)d_in[8];
    const float* bp    = (const float*)d_in[9];
    const float* wd    = (const float*)d_in[10];
    const float* wfc1  = (const float*)d_in[11];
    const float* bfc1  = (const float*)d_in[12];
    const float* wfc2  = (const float*)d_in[13];
    const float* bfc2  = (const float*)d_in[14];
    float* out = (float*)d_out;

    float *xn, *off, *kv, *nrm, *q, *spart, *attn, *proj, *xs2;
    bf16 *xnh, *xnl, *samph, *sampl, *aoh, *aol, *h1h, *h1l, *g1h, *g1l;
    bf16 *wkvh, *wkvl, *wdh, *wdl, *wpjh, *wpjl, *w1h, *w1l, *w2h, *w2l;
    cudaGetSymbolAddress((void**)&xn,    g_xn);
    cudaGetSymbolAddress((void**)&xnh,   g_xnh);
    cudaGetSymbolAddress((void**)&xnl,   g_xnl);
    cudaGetSymbolAddress((void**)&off,   g_off);
    cudaGetSymbolAddress((void**)&samph, g_samph);
    cudaGetSymbolAddress((void**)&sampl, g_sampl);
    cudaGetSymbolAddress((void**)&kv,    g_kv);
    cudaGetSymbolAddress((void**)&nrm,   g_norm);
    cudaGetSymbolAddress((void**)&q,     g_q);
    cudaGetSymbolAddress((void**)&spart, g_spart);
    cudaGetSymbolAddress((void**)&attn,  g_attn);
    cudaGetSymbolAddress((void**)&aoh,   g_aoh);
    cudaGetSymbolAddress((void**)&aol,   g_aol);
    cudaGetSymbolAddress((void**)&proj,  g_proj);
    cudaGetSymbolAddress((void**)&xs2,   g_xs2);
    cudaGetSymbolAddress((void**)&h1h,   g_h1h);
    cudaGetSymbolAddress((void**)&h1l,   g_h1l);
    cudaGetSymbolAddress((void**)&g1h,   g_g1h);
    cudaGetSymbolAddress((void**)&g1l,   g_g1l);
    cudaGetSymbolAddress((void**)&wkvh,  g_wkvh);
    cudaGetSymbolAddress((void**)&wkvl,  g_wkvl);
    cudaGetSymbolAddress((void**)&wdh,   g_wdh);
    cudaGetSymbolAddress((void**)&wdl,   g_wdl);
    cudaGetSymbolAddress((void**)&wpjh,  g_wpjh);
    cudaGetSymbolAddress((void**)&wpjl,  g_wpjl);
    cudaGetSymbolAddress((void**)&w1h,   g_w1h);
    cudaGetSymbolAddress((void**)&w1l,   g_w1l);
    cudaGetSymbolAddress((void**)&w2h,   g_w2h);
    cudaGetSymbolAddress((void**)&w2l,   g_w2l);

    cudaFuncSetAttribute(mma_gemm<0,4>, cudaFuncAttributeMaxDynamicSharedMemorySize, SMEM_GEMM);
    cudaFuncSetAttribute(mma_gemm<0,3>, cudaFuncAttributeMaxDynamicSharedMemorySize, SMEM_GEMM);
    cudaFuncSetAttribute(mma_gemm<1,4>, cudaFuncAttributeMaxDynamicSharedMemorySize, SMEM_GEMM);
    cudaFuncSetAttribute(mma_gemm<2,3>, cudaFuncAttributeMaxDynamicSharedMemorySize, SMEM_GEMM);

    int total = S1 + S2 + S3 + S4 + S5;
    convw_all<<<(total + 255) / 256, 256>>>(wqkv, wd, wproj, wfc1, wfc2,
                                            wkvh, wkvl, wdh, wdl, wpjh, wpjl,
                                            w1h, w1l, w2h, w2l);
    ln1_kernel<<<dim3(BATCH, HW / 32), 256>>>(x, ga1, be1, xn, xnh, xnl);
    offconv_kernel<<<dim3(32, BATCH), 128>>>(xn, wp, bp, off);
    deform_kernel<<<dim3(H_, BATCH, 8), 256>>>(xn, off, samph, sampl);
    // KV: M=384 -> MI=4 (3 tiles of 128)
    mma_gemm<0,4><<<dim3(32, 3, BATCH), 256, SMEM_GEMM>>>(wkvh, wkvl, xnh, xnl, 384, HW, C_,
                                                          kv, nullptr, nullptr, nullptr, nullptr);
    // deform q: M=192 -> MI=3 (2 tiles of 96)
    mma_gemm<0,3><<<dim3(32, 2, BATCH), 256, SMEM_GEMM>>>(wdh, wdl, samph, sampl, C_, HW, KBIG,
                                                          q, nullptr, nullptr, nullptr, nullptr);
    norms_kernel<<<BATCH * 2 * C_, 256>>>(kv, nrm);
    scores_part<<<dim3(BATCH * HEADS, NSPLIT), 256>>>(q, kv, spart);
    scores_fin<<<BATCH * HEADS, dim3(32, 32)>>>(spart, temp, nrm, attn);
    apply_kernel<<<dim3(BATCH * HEADS, HW / 128), 128>>>(attn, kv, nrm, aoh, aol);
    mma_gemm<0,3><<<dim3(32, 2, BATCH), 256, SMEM_GEMM>>>(wpjh, wpjl, aoh, aol, C_, HW, C_,
                                                          proj, nullptr, nullptr, nullptr, nullptr);
    addln_kernel<<<dim3(BATCH, HW / 32), 256>>>(x, proj, ga2, be2, xs2, h1h, h1l);
    mma_gemm<1,4><<<dim3(32, 6, BATCH), 256, SMEM_GEMM>>>(w1h, w1l, h1h, h1l, HID, HW, C_,
                                                          nullptr, g1h, g1l, bfc1, nullptr);
    mma_gemm<2,3><<<dim3(32, 2, BATCH), 256, SMEM_GEMM>>>(w2h, w2l, g1h, g1l, C_, HW, HID,
                                                          out, nullptr, nullptr, bfc2, xs2);
}

// round 17
// speedup vs baseline: 1.6474x; 1.0648x over previous
#include <cuda_runtime.h>
#include <cuda_bf16.h>
#include <math.h>
#include <stdint.h>

#define BATCH 4
#define C_    192
#define H_    64
#define W_    64
#define HW    4096
#define HEADS 6
#define HID   768
#define KBIG  1728   // C_*9
#define NSPLIT 16

typedef __nv_bfloat16 bf16;
typedef unsigned long long u64;

// ---------------- scratch (static device globals; no allocation) ----------------
__device__ float g_xn  [(size_t)BATCH*C_*HW];
__device__ bf16  g_xnh [(size_t)BATCH*C_*HW];
__device__ bf16  g_xnl [(size_t)BATCH*C_*HW];
__device__ float g_off [(size_t)BATCH*18*HW];
__device__ bf16  g_samph[(size_t)BATCH*KBIG*HW];   // hi-only deform samples
__device__ float g_kv  [(size_t)BATCH*2*C_*HW];
__device__ float g_norm[(size_t)BATCH*2*C_];
__device__ float g_q   [(size_t)BATCH*C_*HW];
__device__ float g_spart[(size_t)BATCH*HEADS*NSPLIT*32*32];
__device__ float g_attn[(size_t)BATCH*HEADS*32*32];
__device__ bf16  g_aoh [(size_t)BATCH*C_*HW];
__device__ bf16  g_aol [(size_t)BATCH*C_*HW];
__device__ float g_proj[(size_t)BATCH*C_*HW];
__device__ float g_xs2 [(size_t)BATCH*C_*HW];
__device__ bf16  g_h1h [(size_t)BATCH*C_*HW];
__device__ bf16  g_h1l [(size_t)BATCH*C_*HW];
__device__ bf16  g_g1h [(size_t)BATCH*HID*HW];
__device__ bf16  g_g1l [(size_t)BATCH*HID*HW];
__device__ bf16  g_wkvh[384*C_],  g_wkvl[384*C_];
__device__ bf16  g_wdh [C_*KBIG], g_wdl [C_*KBIG];
__device__ bf16  g_wpjh[C_*C_],   g_wpjl[C_*C_];
__device__ bf16  g_w1h [HID*C_],  g_w1l [HID*C_];
__device__ bf16  g_w2h [C_*HID],  g_w2l [C_*HID];

__device__ __forceinline__ void split_store(float v, bf16* ph, bf16* pl) {
    bf16 h = __float2bfloat16(v);
    *ph = h;
    *pl = __float2bfloat16(v - __bfloat162float(h));
}

#define FMA_F32X2(d, a, b, c) \
    asm("fma.rn.f32x2 %0, %1, %2, %3;" : "=l"(d) : "l"(a), "l"(b), "l"(c))
#define PACK_F32X2(out, lo, hi) \
    asm("mov.b64 %0, {%1, %2};" : "=l"(out) : "f"(lo), "f"(hi))
#define UNPACK_F32X2(lo, hi, in) \
    asm("mov.b64 {%0, %1}, %2;" : "=f"(lo), "=f"(hi) : "l"(in))

// ---------------- merged weight convert ----------------
#define S1 (384*C_)
#define S2 (C_*KBIG)
#define S3 (C_*C_)
#define S4 (HID*C_)
#define S5 (C_*HID)
__global__ void convw_all(const float* __restrict__ wqkv, const float* __restrict__ wd,
                          const float* __restrict__ wproj, const float* __restrict__ wfc1,
                          const float* __restrict__ wfc2,
                          bf16* __restrict__ kvh, bf16* __restrict__ kvl,
                          bf16* __restrict__ dh,  bf16* __restrict__ dl,
                          bf16* __restrict__ pjh, bf16* __restrict__ pjl,
                          bf16* __restrict__ w1h, bf16* __restrict__ w1l,
                          bf16* __restrict__ w2h, bf16* __restrict__ w2l) {
    int i = blockIdx.x * 256 + threadIdx.x;
    if (i < S1) {
        split_store(wqkv[(size_t)C_ * C_ + i], kvh + i, kvl + i);
    } else if (i < S1 + S2) {
        int j = i - S1;
        split_store(wd[j], dh + j, dl + j);
    } else if (i < S1 + S2 + S3) {
        int j = i - S1 - S2;
        split_store(wproj[j], pjh + j, pjl + j);
    } else if (i < S1 + S2 + S3 + S4) {
        int j = i - S1 - S2 - S3;
        int m = j / C_, k = j - m * C_;
        split_store(wfc1[(size_t)k * HID + m], w1h + j, w1l + j);
    } else if (i < S1 + S2 + S3 + S4 + S5) {
        int j = i - S1 - S2 - S3 - S4;
        int m = j / HID, k = j - m * HID;
        split_store(wfc2[(size_t)k * C_ + m], w2h + j, w2l + j);
    }
}

// ---------------- LayerNorm over C, (B,C,HW): f32 + bf16 hi/lo outputs ----------------
__global__ void ln1_kernel(const float* __restrict__ x, const float* __restrict__ g,
                           const float* __restrict__ be, float* __restrict__ out,
                           bf16* __restrict__ oh, bf16* __restrict__ ol) {
    int b = blockIdx.x, hw0 = blockIdx.y * 32;
    __shared__ float tile[C_ * 33];
    __shared__ float mu[32], rs[32];
    int tid = threadIdx.x;
    const float* xb = x + (size_t)b * C_ * HW;
    #pragma unroll
    for (int i = 0; i < 24; i++) {
        int e = i * 256 + tid; int c = e >> 5; int p = e & 31;
        tile[c * 33 + p] = xb[(size_t)c * HW + hw0 + p];
    }
    __syncthreads();
    int warp = tid >> 5, lane = tid & 31;
    #pragma unroll
    for (int s = 0; s < 4; s++) {
        int p = warp * 4 + s;
        float v[6];
        #pragma unroll
        for (int k = 0; k < 6; k++) v[k] = tile[(lane + 32 * k) * 33 + p];
        float sum = 0.f;
        #pragma unroll
        for (int k = 0; k < 6; k++) sum += v[k];
        #pragma unroll
        for (int o = 16; o; o >>= 1) sum += __shfl_xor_sync(0xffffffffu, sum, o);
        float m = sum * (1.f / C_);
        float sq = 0.f;
        #pragma unroll
        for (int k = 0; k < 6; k++) { float d = v[k] - m; sq += d * d; }
        #pragma unroll
        for (int o = 16; o; o >>= 1) sq += __shfl_xor_sync(0xffffffffu, sq, o);
        if (lane == 0) { mu[p] = m; rs[p] = rsqrtf(sq * (1.f / C_) + 1e-5f); }
    }
    __syncthreads();
    #pragma unroll
    for (int i = 0; i < 24; i++) {
        int e = i * 256 + tid; int c = e >> 5; int p = e & 31;
        float v = (tile[c * 33 + p] - mu[p]) * rs[p] * g[c] + be[c];
        size_t o = (size_t)b * C_ * HW + (size_t)c * HW + hw0 + p;
        out[o] = v;
        split_store(v, oh + o, ol + o);
    }
}

// ---------------- residual add + LN2 (channel-major outputs) ----------------
__global__ void addln_kernel(const float* __restrict__ x, const float* __restrict__ pj,
                             const float* __restrict__ g, const float* __restrict__ be,
                             float* __restrict__ xs2, bf16* __restrict__ h1h,
                             bf16* __restrict__ h1l) {
    int b = blockIdx.x, hw0 = blockIdx.y * 32;
    __shared__ float tile[C_ * 33];
    __shared__ float mu[32], rs[32];
    int tid = threadIdx.x;
    const float* xb = x + (size_t)b * C_ * HW;
    const float* pb = pj + (size_t)b * C_ * HW;
    #pragma unroll
    for (int i = 0; i < 24; i++) {
        int e = i * 256 + tid; int c = e >> 5; int p = e & 31;
        tile[c * 33 + p] = xb[(size_t)c * HW + hw0 + p] + pb[(size_t)c * HW + hw0 + p];
    }
    __syncthreads();
    int warp = tid >> 5, lane = tid & 31;
    #pragma unroll
    for (int s = 0; s < 4; s++) {
        int p = warp * 4 + s;
        float v[6];
        #pragma unroll
        for (int k = 0; k < 6; k++) v[k] = tile[(lane + 32 * k) * 33 + p];
        float sum = 0.f;
        #pragma unroll
        for (int k = 0; k < 6; k++) sum += v[k];
        #pragma unroll
        for (int o = 16; o; o >>= 1) sum += __shfl_xor_sync(0xffffffffu, sum, o);
        float m = sum * (1.f / C_);
        float sq = 0.f;
        #pragma unroll
        for (int k = 0; k < 6; k++) { float d = v[k] - m; sq += d * d; }
        #pragma unroll
        for (int o = 16; o; o >>= 1) sq += __shfl_xor_sync(0xffffffffu, sq, o);
        if (lane == 0) { mu[p] = m; rs[p] = rsqrtf(sq * (1.f / C_) + 1e-5f); }
    }
    __syncthreads();
    #pragma unroll
    for (int i = 0; i < 24; i++) {
        int e = i * 256 + tid; int c = e >> 5; int p = e & 31;
        float v = tile[c * 33 + p];
        size_t o = (size_t)b * C_ * HW + (size_t)c * HW + hw0 + p;
        xs2[o] = v;
        float hn = (v - mu[p]) * rs[p] * g[c] + be[c];
        split_store(hn, h1h + o, h1l + o);
    }
}

// ---------------- 3x3 offset conv (18 ch), pad 1: packed f32x2 over channel pairs ----------------
__global__ void offconv_kernel(const float* __restrict__ xn, const float* __restrict__ wp,
                               const float* __restrict__ bp, float* __restrict__ off) {
    __shared__ float2 ws[16 * 162];
    int b = blockIdx.y;
    int h = blockIdx.x * 2 + (threadIdx.x >> 6);
    int w = threadIdx.x & 63;
    int tid = threadIdx.x;
    u64 acc[18];
    #pragma unroll
    for (int j = 0; j < 18; j++) acc[j] = 0ull;
    const float* xb = xn + (size_t)b * C_ * HW;
    for (int c0 = 0; c0 < C_; c0 += 32) {
        __syncthreads();
        for (int e = tid; e < 16 * 162; e += 128) {
            int pr = e / 162, jt = e - pr * 162;
            int j = jt / 9, t = jt - j * 9;
            int ce = c0 + pr * 2;
            ws[e] = make_float2(wp[((size_t)j * C_ + ce) * 9 + t],
                                wp[((size_t)j * C_ + ce + 1) * 9 + t]);
        }
        __syncthreads();
        for (int pr = 0; pr < 16; pr++) {
            const float* xc0 = xb + (size_t)(c0 + pr * 2) * HW;
            const float* xc1 = xc0 + HW;
            u64 vv[9];
            #pragma unroll
            for (int di = 0; di < 3; di++)
                #pragma unroll
                for (int dj = 0; dj < 3; dj++) {
                    int hh = h + di - 1, ww = w + dj - 1;
                    float a = 0.f, c = 0.f;
                    if (hh >= 0 && hh < H_ && ww >= 0 && ww < W_) {
                        a = __ldg(xc0 + hh * W_ + ww);
                        c = __ldg(xc1 + hh * W_ + ww);
                    }
                    PACK_F32X2(vv[di * 3 + dj], a, c);
                }
            const float2* wr = ws + pr * 162;
            #pragma unroll
            for (int j = 0; j < 18; j++)
                #pragma unroll
                for (int t = 0; t < 9; t++) {
                    u64 wv = *(const u64*)&wr[j * 9 + t];
                    FMA_F32X2(acc[j], wv, vv[t], acc[j]);
                }
        }
    }
    #pragma unroll
    for (int j = 0; j < 18; j++) {
        float lo, hi;
        UNPACK_F32X2(lo, hi, acc[j]);
        off[((size_t)b * 18 + j) * HW + h * W_ + w] = lo + hi + bp[j];
    }
}

// ---------------- deformable bilinear sampling, hi-only bf16 output ----------------
__global__ void deform_kernel(const float* __restrict__ xn, const float* __restrict__ off,
                              bf16* __restrict__ sh) {
    int h = blockIdx.x, b = blockIdx.y;
    int cg = blockIdx.z * 8 + (threadIdx.x >> 5);   // 64 groups of 3 channels
    int w = (threadIdx.x & 31) * 2;
    int hw = h * W_ + w;
    const float* xb = xn + (size_t)b * C_ * HW;
    const float* ob = off + (size_t)b * 18 * HW;
    bf16* sbh = sh + (size_t)b * KBIG * HW;
    const float HB = (float)(H_ + 1), WB = (float)(W_ + 1);
    for (int n = 0; n < 9; n++) {
        float g0[4], g1[4];
        int o0[4], o1[4];
        bool v0[4], v1[4];
        #pragma unroll
        for (int p = 0; p < 2; p++) {
            float ox = ob[(size_t)n * HW + hw + p];
            float oy = ob[(size_t)(9 + n) * HW + hw + p];
            float px = (float)(h + n / 3) + ox;
            float py = (float)(w + p + n % 3) + oy;
            float fx = floorf(px), fy = floorf(py);
            float qlx = fminf(fmaxf(fx, 0.f), HB);
            float qrx = fminf(fmaxf(fx + 1.f, 0.f), HB);
            float qly = fminf(fmaxf(fy, 0.f), WB);
            float qry = fminf(fmaxf(fy + 1.f, 0.f), WB);
            float pxc = fminf(fmaxf(px, 0.f), HB);
            float pyc = fminf(fmaxf(py, 0.f), WB);
            float glt = (1.f + qlx - pxc) * (1.f + qly - pyc);
            float grb = (1.f - qrx + pxc) * (1.f - qry + pyc);
            float glb = (1.f + qlx - pxc) * (1.f - qry + pyc);
            float grt = (1.f - qrx + pxc) * (1.f + qly - pyc);
            int ilx = (int)qlx, irx = (int)qrx, ily = (int)qly, iry = (int)qry;
            bool vlx = (ilx >= 1 && ilx <= H_), vrx = (irx >= 1 && irx <= H_);
            bool vly = (ily >= 1 && ily <= W_), vry = (iry >= 1 && iry <= W_);
            float* g = p ? g1 : g0; int* oo = p ? o1 : o0; bool* vb = p ? v1 : v0;
            g[0] = glt; oo[0] = (ilx - 1) * W_ + (ily - 1); vb[0] = vlx && vly;
            g[1] = grb; oo[1] = (irx - 1) * W_ + (iry - 1); vb[1] = vrx && vry;
            g[2] = glb; oo[2] = (ilx - 1) * W_ + (iry - 1); vb[2] = vlx && vry;
            g[3] = grt; oo[3] = (irx - 1) * W_ + (ily - 1); vb[3] = vrx && vly;
        }
        int c0 = cg * 3;
        #pragma unroll
        for (int c = c0; c < c0 + 3; c++) {
            const float* xc = xb + (size_t)c * HW;
            float a = 0.f, bb = 0.f;
            #pragma unroll
            for (int t = 0; t < 4; t++) {
                if (v0[t]) a  += g0[t] * __ldg(xc + o0[t]);
                if (v1[t]) bb += g1[t] * __ldg(xc + o1[t]);
            }
            size_t o = ((size_t)c * 9 + n) * HW + hw;
            __nv_bfloat162 hv;
            hv.x = __float2bfloat16(a);
            hv.y = __float2bfloat16(bb);
            *reinterpret_cast<__nv_bfloat162*>(sbh + o) = hv;
        }
    }
}

// ---------------- row L2 norms over HW -> reciprocal norms ----------------
__global__ void norms_kernel(const float* __restrict__ kv, float* __restrict__ nrm) {
    int row = blockIdx.x;
    const float* p = kv + (size_t)row * HW;
    int tid = threadIdx.x;
    float s = 0.f;
    for (int i = tid; i < HW; i += 256) { float v = p[i]; s += v * v; }
    __shared__ float red[8];
    #pragma unroll
    for (int o = 16; o; o >>= 1) s += __shfl_xor_sync(0xffffffffu, s, o);
    if ((tid & 31) == 0) red[tid >> 5] = s;
    __syncthreads();
    if (tid == 0) {
        float t = 0.f;
        #pragma unroll
        for (int i = 0; i < 8; i++) t += red[i];
        nrm[row] = 1.f / fmaxf(sqrtf(t), 1e-12f);
    }
}

// ---------------- attention scores: split-K partials ----------------
__global__ void scores_part(const float* __restrict__ q, const float* __restrict__ kv,
                            float* __restrict__ spart) {
    int bh = blockIdx.x, s = blockIdx.y;
    int b = bh / HEADS, hh = bh % HEADS;
    int tid = threadIdx.x;
    int tx = tid & 15, ty = tid >> 4;
    __shared__ float qs[32 * 65], ks[32 * 65];
    const float* qrow = q + ((size_t)b * C_ + hh * 32) * HW;
    const float* krow = kv + ((size_t)b * 2 * C_ + hh * 32) * HW;
    float a00 = 0.f, a01 = 0.f, a10 = 0.f, a11 = 0.f;
    const int CH = HW / NSPLIT;
    for (int ch = s * CH; ch < s * CH + CH; ch += 64) {
        #pragma unroll
        for (int i = 0; i < 8; i++) {
            int e = i * 256 + tid; int r = e >> 6, col = e & 63;
            qs[r * 65 + col] = qrow[(size_t)r * HW + ch + col];
            ks[r * 65 + col] = krow[(size_t)r * HW + ch + col];
        }
        __syncthreads();
        #pragma unroll
        for (int t = 0; t < 64; t++) {
            float q0 = qs[(2 * ty) * 65 + t], q1 = qs[(2 * ty + 1) * 65 + t];
            float k0 = ks[(2 * tx) * 65 + t], k1 = ks[(2 * tx + 1) * 65 + t];
            a00 += q0 * k0; a01 += q0 * k1; a10 += q1 * k0; a11 += q1 * k1;
        }
        __syncthreads();
    }
    float* sp = spart + ((size_t)bh * NSPLIT + s) * 1024;
    sp[(2 * ty) * 32 + 2 * tx] = a00;
    sp[(2 * ty) * 32 + 2 * tx + 1] = a01;
    sp[(2 * ty + 1) * 32 + 2 * tx] = a10;
    sp[(2 * ty + 1) * 32 + 2 * tx + 1] = a11;
}

// ---------------- scores finalize: reduce + knorm + temp + softmax ----------------
__global__ void scores_fin(const float* __restrict__ spart, const float* __restrict__ temp,
                           const float* __restrict__ nrm, float* __restrict__ attn) {
    int bh = blockIdx.x, hh = bh % HEADS;
    int b = bh / HEADS;
    int d = threadIdx.x, c = threadIdx.y;
    float v = 0.f;
    #pragma unroll
    for (int s = 0; s < NSPLIT; s++)
        v += spart[(((size_t)bh * NSPLIT + s) * 32 + c) * 32 + d];
    v *= nrm[b * 2 * C_ + hh * 32 + d] * temp[hh];
    float m = v;
    #pragma unroll
    for (int o = 16; o; o >>= 1) m = fmaxf(m, __shfl_xor_sync(0xffffffffu, m, o));
    float e = expf(v - m);
    float su = e;
    #pragma unroll
    for (int o = 16; o; o >>= 1) su += __shfl_xor_sync(0xffffffffu, su, o);
    attn[((size_t)bh * 32 + c) * 32 + d] = e / su;
}

// ---------------- attention apply (vnorm folded into attn) -> bf16 hi/lo ----------------
__global__ void apply_kernel(const float* __restrict__ attn, const float* __restrict__ kv,
                             const float* __restrict__ nrm,
                             bf16* __restrict__ aoh, bf16* __restrict__ aol) {
    int bh = blockIdx.x; int b = bh / HEADS, hh = bh % HEADS;
    int tid = threadIdx.x;
    int n = blockIdx.y * 128 + tid;
    __shared__ float a[32][32];
    #pragma unroll
    for (int i = 0; i < 8; i++) {
        int e = i * 128 + tid;
        int dd = e & 31;
        a[e >> 5][dd] = attn[(size_t)bh * 1024 + e] * nrm[b * 2 * C_ + C_ + hh * 32 + dd];
    }
    __syncthreads();
    const float* vrow = kv + ((size_t)b * 2 * C_ + C_ + hh * 32) * HW;
    float acc[32];
    #pragma unroll
    for (int c = 0; c < 32; c++) acc[c] = 0.f;
    for (int dd = 0; dd < 32; dd++) {
        float v = vrow[(size_t)dd * HW + n];
        #pragma unroll
        for (int c = 0; c < 32; c++) acc[c] += a[c][dd] * v;
    }
    size_t ob = ((size_t)b * C_ + hh * 32) * HW + n;
    #pragma unroll
    for (int c = 0; c < 32; c++)
        split_store(acc[c], aoh + ob + (size_t)c * HW, aol + ob + (size_t)c * HW);
}

// ================= bf16 split tensor-core GEMM with 2-stage cp.async pipeline =================
// BLO: whether B has a lo plane (3-term split) or hi-only (2-term: Ah*Bh + Al*Bh).
#define APITCH 40
#define BPITCH 136
#define ASTG (128 * APITCH)
#define BSTG (32 * BPITCH)
#define SMEM_GEMM ((2 * ASTG * 2 + 2 * BSTG * 2) * 2)      // 75776 (BLO=true)
#define SMEM_GEMM_NB ((2 * ASTG * 2 + 2 * BSTG) * 2)       // 58368 (BLO=false)

__device__ __forceinline__ uint32_t cvta_s(const void* p) {
    return (uint32_t)__cvta_generic_to_shared(p);
}
__device__ __forceinline__ void cp_async16(uint32_t d, const void* s, int sz) {
    asm volatile("cp.async.cg.shared.global [%0], [%1], 16, %2;" :: "r"(d), "l"(s), "r"(sz));
}
__device__ __forceinline__ void cp_commit() { asm volatile("cp.async.commit_group;"); }
__device__ __forceinline__ void cp_wait1() { asm volatile("cp.async.wait_group 1;"); }
__device__ __forceinline__ void cp_wait0() { asm volatile("cp.async.wait_group 0;"); }

__device__ __forceinline__ void ldsm_x4(uint32_t* r, uint32_t a) {
    asm volatile("ldmatrix.sync.aligned.m8n8.x4.shared.b16 {%0,%1,%2,%3}, [%4];"
                 : "=r"(r[0]), "=r"(r[1]), "=r"(r[2]), "=r"(r[3]) : "r"(a));
}
__device__ __forceinline__ void ldsm_x4t(uint32_t* r, uint32_t a) {
    asm volatile("ldmatrix.sync.aligned.m8n8.x4.trans.shared.b16 {%0,%1,%2,%3}, [%4];"
                 : "=r"(r[0]), "=r"(r[1]), "=r"(r[2]), "=r"(r[3]) : "r"(a));
}
__device__ __forceinline__ void mma_bf16(float* c, const uint32_t* a, const uint32_t* b) {
    asm volatile("mma.sync.aligned.m16n8k16.row.col.f32.bf16.bf16.f32 "
                 "{%0,%1,%2,%3}, {%4,%5,%6,%7}, {%8,%9}, {%0,%1,%2,%3};"
                 : "+f"(c[0]), "+f"(c[1]), "+f"(c[2]), "+f"(c[3])
                 : "r"(a[0]), "r"(a[1]), "r"(a[2]), "r"(a[3]), "r"(b[0]), "r"(b[1]));
}

template<int EP, int MI, bool BLO>
__global__ void __launch_bounds__(256, 2)
mma_gemm(const bf16* __restrict__ Ah, const bf16* __restrict__ Al,
         const bf16* __restrict__ Bh, const bf16* __restrict__ Bl,
         int M, int N, int K,
         float* __restrict__ Cf, bf16* __restrict__ Oh, bf16* __restrict__ Ol,
         const float* __restrict__ bias, const float* __restrict__ res) {
    extern __shared__ char smem[];
    bf16* AsH = (bf16*)smem;
    bf16* AsL = AsH + 2 * ASTG;
    bf16* BsH = AsL + 2 * ASTG;
    bf16* BsL = BsH + 2 * BSTG;   // unused when !BLO
    const int BM = MI * 32;

    int z = blockIdx.z;
    size_t bOff = (size_t)z * K * N;
    size_t cOff = (size_t)z * M * N;
    int n0 = blockIdx.x * 128, m0 = blockIdx.y * BM;
    int tid = threadIdx.x, lane = tid & 31, warp = tid >> 5;
    int wm = (warp & 1) * (MI * 16), wn = (warp >> 1) * 32;
    float acc[MI][4][4];
    #pragma unroll
    for (int i = 0; i < MI; i++)
        #pragma unroll
        for (int j = 0; j < 4; j++)
            #pragma unroll
            for (int t = 0; t < 4; t++) acc[i][j][t] = 0.f;

    int nk = K >> 5;
    auto load_stage = [&](int st, int kt) {
        int k0 = kt << 5;
        bf16* aH = AsH + st * ASTG;
        bf16* aL = AsL + st * ASTG;
        bf16* bH = BsH + st * BSTG;
        bf16* bL = BsL + st * BSTG;
        #pragma unroll
        for (int i = 0; i < 2; i++) {
            int e = i * 256 + tid;
            if (e >= BM * 4) break;
            int r = e >> 2, qc = e & 3;
            int gr = m0 + r;
            int sz = (gr < M) ? 16 : 0;
            if (gr >= M) gr = M - 1;
            cp_async16(cvta_s(aH + r * APITCH + qc * 8), Ah + (size_t)gr * K + k0 + qc * 8, sz);
            cp_async16(cvta_s(aL + r * APITCH + qc * 8), Al + (size_t)gr * K + k0 + qc * 8, sz);
        }
        #pragma unroll
        for (int i = 0; i < 2; i++) {
            int e = i * 256 + tid;
            int r = e >> 4, qc = e & 15;
            const bf16* sH = Bh + bOff + (size_t)(k0 + r) * N + n0 + qc * 8;
            cp_async16(cvta_s(bH + r * BPITCH + qc * 8), sH, 16);
            if (BLO) {
                const bf16* sL = Bl + bOff + (size_t)(k0 + r) * N + n0 + qc * 8;
                cp_async16(cvta_s(bL + r * BPITCH + qc * 8), sL, 16);
            }
        }
    };

    load_stage(0, 0);
    cp_commit();
    for (int kt = 0; kt < nk; kt++) {
        int st = kt & 1;
        bool more = (kt + 1 < nk);
        if (more) { load_stage(st ^ 1, kt + 1); cp_commit(); }
        if (more) cp_wait1(); else cp_wait0();
        __syncthreads();
        bf16* aH = AsH + st * ASTG;
        bf16* aL = AsL + st * ASTG;
        bf16* bH = BsH + st * BSTG;
        bf16* bL = BsL + st * BSTG;
        #pragma unroll
        for (int kk = 0; kk < 32; kk += 16) {
            uint32_t fbh[4][2], fbl[4][2];
            int brow = kk + (lane & 15);
            int nsel = (lane >> 4);
            #pragma unroll
            for (int ni = 0; ni < 4; ni += 2) {
                uint32_t tmp[4];
                ldsm_x4t(tmp, cvta_s(bH + brow * BPITCH + wn + (ni + nsel) * 8));
                fbh[ni][0] = tmp[0]; fbh[ni][1] = tmp[1];
                fbh[ni + 1][0] = tmp[2]; fbh[ni + 1][1] = tmp[3];
                if (BLO) {
                    ldsm_x4t(tmp, cvta_s(bL + brow * BPITCH + wn + (ni + nsel) * 8));
                    fbl[ni][0] = tmp[0]; fbl[ni][1] = tmp[1];
                    fbl[ni + 1][0] = tmp[2]; fbl[ni + 1][1] = tmp[3];
                }
            }
            int arow = wm + (lane & 15);
            int acol = kk + ((lane >> 4) << 3);
            #pragma unroll
            for (int mi = 0; mi < MI; mi++) {
                uint32_t fah[4], fal[4];
                ldsm_x4(fah, cvta_s(aH + (arow + mi * 16) * APITCH + acol));
                ldsm_x4(fal, cvta_s(aL + (arow + mi * 16) * APITCH + acol));
                #pragma unroll
                for (int ni = 0; ni < 4; ni++) {
                    mma_bf16(acc[mi][ni], fah, fbh[ni]);
                    if (BLO) mma_bf16(acc[mi][ni], fah, fbl[ni]);
                    mma_bf16(acc[mi][ni], fal, fbh[ni]);
                }
            }
        }
        __syncthreads();
    }

    int gid = lane >> 2, tig = lane & 3;
    #pragma unroll
    for (int mi = 0; mi < MI; mi++) {
        #pragma unroll
        for (int ni = 0; ni < 4; ni++) {
            #pragma unroll
            for (int half = 0; half < 2; half++) {
                int row = m0 + wm + mi * 16 + gid + half * 8;
                if (row >= M) continue;
                int col = n0 + wn + ni * 8 + tig * 2;
                #pragma unroll
                for (int j = 0; j < 2; j++) {
                    float v = acc[mi][ni][half * 2 + j];
                    size_t o = cOff + (size_t)row * N + col + j;
                    if (EP == 0) {
                        Cf[o] = v;
                    } else if (EP == 1) {
                        v += bias[row];
                        v = 0.5f * v * (1.f + erff(v * 0.70710678118654752f));
                        split_store(v, Oh + o, Ol + o);
                    } else {
                        v += bias[row] + res[o];
                        Cf[o] = v;
                    }
                }
            }
        }
    }
}

// ---------------- launch (single stream) ----------------
extern "C" void kernel_launch(void* const* d_in, const int* in_sizes, int n_in,
                              void* d_out, int out_size) {
    const float* x     = (const float*)d_in[0];
    const float* ga1   = (const float*)d_in[1];
    const float* be1   = (const float*)d_in[2];
    const float* ga2   = (const float*)d_in[3];
    const float* be2   = (const float*)d_in[4];
    const float* temp  = (const float*)d_in[5];
    const float* wqkv  = (const float*)d_in[6];
    const float* wproj = (const float*)d_in[7];
    const float* wp    = (const float*)d_in[8];
    const float* bp    = (const float*)d_in[9];
    const float* wd    = (const float*)d_in[10];
    const float* wfc1  = (const float*)d_in[11];
    const float* bfc1  = (const float*)d_in[12];
    const float* wfc2  = (const float*)d_in[13];
    const float* bfc2  = (const float*)d_in[14];
    float* out = (float*)d_out;

    float *xn, *off, *kv, *nrm, *q, *spart, *attn, *proj, *xs2;
    bf16 *xnh, *xnl, *samph, *aoh, *aol, *h1h, *h1l, *g1h, *g1l;
    bf16 *wkvh, *wkvl, *wdh, *wdl, *wpjh, *wpjl, *w1h, *w1l, *w2h, *w2l;
    cudaGetSymbolAddress((void**)&xn,    g_xn);
    cudaGetSymbolAddress((void**)&xnh,   g_xnh);
    cudaGetSymbolAddress((void**)&xnl,   g_xnl);
    cudaGetSymbolAddress((void**)&off,   g_off);
    cudaGetSymbolAddress((void**)&samph, g_samph);
    cudaGetSymbolAddress((void**)&kv,    g_kv);
    cudaGetSymbolAddress((void**)&nrm,   g_norm);
    cudaGetSymbolAddress((void**)&q,     g_q);
    cudaGetSymbolAddress((void**)&spart, g_spart);
    cudaGetSymbolAddress((void**)&attn,  g_attn);
    cudaGetSymbolAddress((void**)&aoh,   g_aoh);
    cudaGetSymbolAddress((void**)&aol,   g_aol);
    cudaGetSymbolAddress((void**)&proj,  g_proj);
    cudaGetSymbolAddress((void**)&xs2,   g_xs2);
    cudaGetSymbolAddress((void**)&h1h,   g_h1h);
    cudaGetSymbolAddress((void**)&h1l,   g_h1l);
    cudaGetSymbolAddress((void**)&g1h,   g_g1h);
    cudaGetSymbolAddress((void**)&g1l,   g_g1l);
    cudaGetSymbolAddress((void**)&wkvh,  g_wkvh);
    cudaGetSymbolAddress((void**)&wkvl,  g_wkvl);
    cudaGetSymbolAddress((void**)&wdh,   g_wdh);
    cudaGetSymbolAddress((void**)&wdl,   g_wdl);
    cudaGetSymbolAddress((void**)&wpjh,  g_wpjh);
    cudaGetSymbolAddress((void**)&wpjl,  g_wpjl);
    cudaGetSymbolAddress((void**)&w1h,   g_w1h);
    cudaGetSymbolAddress((void**)&w1l,   g_w1l);
    cudaGetSymbolAddress((void**)&w2h,   g_w2h);
    cudaGetSymbolAddress((void**)&w2l,   g_w2l);

    cudaFuncSetAttribute(mma_gemm<0,4,true>,  cudaFuncAttributeMaxDynamicSharedMemorySize, SMEM_GEMM);
    cudaFuncSetAttribute(mma_gemm<0,3,false>, cudaFuncAttributeMaxDynamicSharedMemorySize, SMEM_GEMM_NB);
    cudaFuncSetAttribute(mma_gemm<0,3,true>,  cudaFuncAttributeMaxDynamicSharedMemorySize, SMEM_GEMM);
    cudaFuncSetAttribute(mma_gemm<1,4,true>,  cudaFuncAttributeMaxDynamicSharedMemorySize, SMEM_GEMM);
    cudaFuncSetAttribute(mma_gemm<2,3,true>,  cudaFuncAttributeMaxDynamicSharedMemorySize, SMEM_GEMM);

    int total = S1 + S2 + S3 + S4 + S5;
    convw_all<<<(total + 255) / 256, 256>>>(wqkv, wd, wproj, wfc1, wfc2,
                                            wkvh, wkvl, wdh, wdl, wpjh, wpjl,
                                            w1h, w1l, w2h, w2l);
    ln1_kernel<<<dim3(BATCH, HW / 32), 256>>>(x, ga1, be1, xn, xnh, xnl);
    offconv_kernel<<<dim3(32, BATCH), 128>>>(xn, wp, bp, off);
    deform_kernel<<<dim3(H_, BATCH, 8), 256>>>(xn, off, samph);
    // KV: M=384, 3-term split
    mma_gemm<0,4,true><<<dim3(32, 3, BATCH), 256, SMEM_GEMM>>>(
        wkvh, wkvl, xnh, xnl, 384, HW, C_, kv, nullptr, nullptr, nullptr, nullptr);
    // deform q: M=192, B hi-only (2-term split)
    mma_gemm<0,3,false><<<dim3(32, 2, BATCH), 256, SMEM_GEMM_NB>>>(
        wdh, wdl, samph, samph, C_, HW, KBIG, q, nullptr, nullptr, nullptr, nullptr);
    norms_kernel<<<BATCH * 2 * C_, 256>>>(kv, nrm);
    scores_part<<<dim3(BATCH * HEADS, NSPLIT), 256>>>(q, kv, spart);
    scores_fin<<<BATCH * HEADS, dim3(32, 32)>>>(spart, temp, nrm, attn);
    apply_kernel<<<dim3(BATCH * HEADS, HW / 128), 128>>>(attn, kv, nrm, aoh, aol);
    mma_gemm<0,3,true><<<dim3(32, 2, BATCH), 256, SMEM_GEMM>>>(
        wpjh, wpjl, aoh, aol, C_, HW, C_, proj, nullptr, nullptr, nullptr, nullptr);
    addln_kernel<<<dim3(BATCH, HW / 32), 256>>>(x, proj, ga2, be2, xs2, h1h, h1l);
    mma_gemm<1,4,true><<<dim3(32, 6, BATCH), 256, SMEM_GEMM>>>(
        w1h, w1l, h1h, h1l, HID, HW, C_, nullptr, g1h, g1l, bfc1, nullptr);
    mma_gemm<2,3,true><<<dim3(32, 2, BATCH), 256, SMEM_GEMM>>>(
        w2h, w2l, g1h, g1l, C_, HW, HID, out, nullptr, nullptr, bfc2, xs2);
}